// round 4
// baseline (speedup 1.0000x reference)
#include <cuda_runtime.h>
#include <math.h>

// ---------------------------------------------------------------------------
// WaveInterference: full-hidden attention layer, fp32 throughout.
//   Q = x@Wq^T+bq ; K = x@Wk^T+bk ; V = x@Wv^T+bv
//   S = (Q K^T) / sqrt(512)  -> softmax rows -> O = S V -> out = O@Wo^T+bo
// B=4, S=4096, H=1024. All dims multiples of 128 -> no edge handling.
// ---------------------------------------------------------------------------

#define BATCH 4
#define SEQL  4096
#define HID   1024
#define MTOT  (BATCH * SEQL)   // 16384

// Scratch: static device globals (no allocs allowed in kernel_launch).
__device__ float g_Q[(size_t)MTOT * HID];          //  64 MB
__device__ float g_K[(size_t)MTOT * HID];          //  64 MB
__device__ float g_V[(size_t)MTOT * HID];          //  64 MB
__device__ float g_S[(size_t)BATCH * SEQL * SEQL]; // 256 MB
__device__ float g_O[(size_t)MTOT * HID];          //  64 MB

// ---------------------------------------------------------------------------
// 128x128 tiled fp32 GEMM, BK=8, 256 threads, 8x8 per thread.
//   BT = true : C = alpha * A[M,K] * B[N,K]^T (+bias)   (both K-major, "NT")
//   BT = false: C = alpha * A[M,K] * B[K,N]   (+bias)   ("NN")
// Batched via blockIdx.z with explicit strides (0 strides = shared operand).
// ---------------------------------------------------------------------------
template <bool BT>
__global__ __launch_bounds__(256) void gemm128(
    const float* __restrict__ A, const float* __restrict__ B,
    const float* __restrict__ bias, float* __restrict__ C,
    int M, int N, int K, float alpha,
    long long sA, long long sB, long long sC)
{
    const float* Ab = A + (long long)blockIdx.z * sA;
    const float* Bb = B + (long long)blockIdx.z * sB;
    float*       Cb = C + (long long)blockIdx.z * sC;

    __shared__ float As[8][128];
    __shared__ float Bs[8][128];

    const int tid = threadIdx.x;
    const int tx  = tid & 15;          // 0..15 -> 8 cols each
    const int ty  = tid >> 4;          // 0..15 -> 8 rows each
    const int m0  = blockIdx.y * 128;
    const int n0  = blockIdx.x * 128;

    // A (and BT-B) tile load mapping: 128 rows x 8 k  = 256 float4
    const int lrow  = tid >> 1;        // 0..127
    const int lcol  = (tid & 1) * 4;   // 0 or 4
    // NN-B tile load mapping: 8 k-rows x 128 n = 256 float4
    const int nbrow = tid >> 5;        // 0..7
    const int nbcol = (tid & 31) * 4;  // 0..124

    float acc[8][8];
#pragma unroll
    for (int i = 0; i < 8; i++)
#pragma unroll
        for (int j = 0; j < 8; j++) acc[i][j] = 0.0f;

    for (int k0 = 0; k0 < K; k0 += 8) {
        // --- load A tile (transpose into As[k][m]) ---
        float4 av = *(const float4*)&Ab[(long long)(m0 + lrow) * K + (k0 + lcol)];
        As[lcol + 0][lrow] = av.x;
        As[lcol + 1][lrow] = av.y;
        As[lcol + 2][lrow] = av.z;
        As[lcol + 3][lrow] = av.w;

        // --- load B tile into Bs[k][n] ---
        if (BT) {
            float4 bv = *(const float4*)&Bb[(long long)(n0 + lrow) * K + (k0 + lcol)];
            Bs[lcol + 0][lrow] = bv.x;
            Bs[lcol + 1][lrow] = bv.y;
            Bs[lcol + 2][lrow] = bv.z;
            Bs[lcol + 3][lrow] = bv.w;
        } else {
            float4 bv = *(const float4*)&Bb[(long long)(k0 + nbrow) * N + (n0 + nbcol)];
            *(float4*)&Bs[nbrow][nbcol] = bv;
        }
        __syncthreads();

#pragma unroll
        for (int kk = 0; kk < 8; kk++) {
            float a[8], b[8];
            *(float4*)&a[0] = *(const float4*)&As[kk][ty * 8 + 0];
            *(float4*)&a[4] = *(const float4*)&As[kk][ty * 8 + 4];
            *(float4*)&b[0] = *(const float4*)&Bs[kk][tx * 8 + 0];
            *(float4*)&b[4] = *(const float4*)&Bs[kk][tx * 8 + 4];
#pragma unroll
            for (int i = 0; i < 8; i++)
#pragma unroll
                for (int j = 0; j < 8; j++)
                    acc[i][j] = fmaf(a[i], b[j], acc[i][j]);
        }
        __syncthreads();
    }

    // --- epilogue: scale, bias, vectorized store ---
#pragma unroll
    for (int i = 0; i < 8; i++) {
        const int row = m0 + ty * 8 + i;
#pragma unroll
        for (int j = 0; j < 8; j += 4) {
            const int col = n0 + tx * 8 + j;
            float4 v;
            v.x = acc[i][j + 0] * alpha;
            v.y = acc[i][j + 1] * alpha;
            v.z = acc[i][j + 2] * alpha;
            v.w = acc[i][j + 3] * alpha;
            if (bias) {
                v.x += bias[col + 0];
                v.y += bias[col + 1];
                v.z += bias[col + 2];
                v.w += bias[col + 3];
            }
            *(float4*)&Cb[(long long)row * N + col] = v;
        }
    }
}

// ---------------------------------------------------------------------------
// Row softmax, in place. One block (256 threads) per 4096-wide row.
// ---------------------------------------------------------------------------
__global__ __launch_bounds__(256) void softmax_rows(float* __restrict__ S)
{
    float* row = S + (size_t)blockIdx.x * SEQL;
    const int tid = threadIdx.x;
    __shared__ float red[256];

    float vals[16];
    float lmax = -3.402823e38f;
#pragma unroll
    for (int i = 0; i < 4; i++) {
        float4 t = *(const float4*)&row[(tid + i * 256) * 4];
        vals[i * 4 + 0] = t.x; vals[i * 4 + 1] = t.y;
        vals[i * 4 + 2] = t.z; vals[i * 4 + 3] = t.w;
        lmax = fmaxf(lmax, fmaxf(fmaxf(t.x, t.y), fmaxf(t.z, t.w)));
    }

    red[tid] = lmax;
    __syncthreads();
#pragma unroll
    for (int s = 128; s > 0; s >>= 1) {
        if (tid < s) red[tid] = fmaxf(red[tid], red[tid + s]);
        __syncthreads();
    }
    const float m = red[0];
    __syncthreads();

    float lsum = 0.0f;
#pragma unroll
    for (int i = 0; i < 16; i++) {
        vals[i] = expf(vals[i] - m);
        lsum += vals[i];
    }
    red[tid] = lsum;
    __syncthreads();
#pragma unroll
    for (int s = 128; s > 0; s >>= 1) {
        if (tid < s) red[tid] += red[tid + s];
        __syncthreads();
    }
    const float inv = 1.0f / red[0];

#pragma unroll
    for (int i = 0; i < 4; i++) {
        float4 t;
        t.x = vals[i * 4 + 0] * inv; t.y = vals[i * 4 + 1] * inv;
        t.z = vals[i * 4 + 2] * inv; t.w = vals[i * 4 + 3] * inv;
        *(float4*)&row[(tid + i * 256) * 4] = t;
    }
}

// ---------------------------------------------------------------------------
extern "C" void kernel_launch(void* const* d_in, const int* in_sizes, int n_in,
                              void* d_out, int out_size)
{
    (void)in_sizes; (void)n_in; (void)out_size;
    const float* x  = (const float*)d_in[0];
    const float* Wq = (const float*)d_in[1];
    const float* bq = (const float*)d_in[2];
    const float* Wk = (const float*)d_in[3];
    const float* bk = (const float*)d_in[4];
    const float* Wv = (const float*)d_in[5];
    const float* bv = (const float*)d_in[6];
    const float* Wo = (const float*)d_in[7];
    const float* bo = (const float*)d_in[8];
    float* out = (float*)d_out;

    float *Q, *K, *V, *S, *O;
    cudaGetSymbolAddress((void**)&Q, g_Q);
    cudaGetSymbolAddress((void**)&K, g_K);
    cudaGetSymbolAddress((void**)&V, g_V);
    cudaGetSymbolAddress((void**)&S, g_S);
    cudaGetSymbolAddress((void**)&O, g_O);

    const dim3 blk(256);
    const long long strideQKV = (long long)SEQL * HID;   // per-batch Q/K/V/O stride
    const long long strideS   = (long long)SEQL * SEQL;  // per-batch scores stride
    const float score_scale = 0.044194173824159216f;     // 1/sqrt(512)

    // Q/K/V projections: [16384,1024] = x[16384,1024] @ W[1024,1024]^T + b
    dim3 gProj(HID / 128, MTOT / 128, 1);
    gemm128<true><<<gProj, blk>>>(x, Wq, bq, Q, MTOT, HID, HID, 1.0f, 0, 0, 0);
    gemm128<true><<<gProj, blk>>>(x, Wk, bk, K, MTOT, HID, HID, 1.0f, 0, 0, 0);
    gemm128<true><<<gProj, blk>>>(x, Wv, bv, V, MTOT, HID, HID, 1.0f, 0, 0, 0);

    // scores[b] = Q[b] @ K[b]^T / sqrt(512) : per-batch [4096,4096], K=1024
    dim3 gScore(SEQL / 128, SEQL / 128, BATCH);
    gemm128<true><<<gScore, blk>>>(Q, K, nullptr, S, SEQL, SEQL, HID,
                                   score_scale, strideQKV, strideQKV, strideS);

    // softmax over every row of scores
    softmax_rows<<<BATCH * SEQL, blk>>>(S);

    // O[b] = weights[b] @ V[b] : per-batch [4096,1024], K=4096, B is [K,N]
    dim3 gPV(HID / 128, SEQL / 128, BATCH);
    gemm128<false><<<gPV, blk>>>(S, V, nullptr, O, SEQL, HID, SEQL,
                                 1.0f, strideS, strideQKV, strideQKV);

    // out = O @ Wo^T + bo : [16384,1024]
    gemm128<true><<<gProj, blk>>>(O, Wo, bo, out, MTOT, HID, HID, 1.0f, 0, 0, 0);
}

// round 9
// speedup vs baseline: 3.4150x; 3.4150x over previous
#include <cuda_runtime.h>
#include <cuda_bf16.h>
#include <stdint.h>
#include <math.h>

// ---------------------------------------------------------------------------
// WaveInterference via warp-level bf16 mma.sync (base-target PTX; no tcgen05).
// fp32 accuracy through hi/lo bf16 split, 3-pass accumulation.
// B=4, S=4096, H=1024.
// ---------------------------------------------------------------------------

#define BATCH 4
#define SEQL  4096
#define HID   1024
#define MTOT  (BATCH * SEQL)   // 16384

#define BM 128
#define BN 128
#define BK 32
#define TILE_B  8192               // 128 rows x 64 B (32 bf16)
#define STAGE_B (4 * TILE_B)       // Ah, Al, Bh, Bl
#define SMEM_TOTAL (2 * STAGE_B)   // 65536

// ---------------------------------------------------------------------------
// Device scratch (no allocs allowed anywhere).
// ---------------------------------------------------------------------------
__device__ __nv_bfloat16 g_xh[(size_t)MTOT * HID];
__device__ __nv_bfloat16 g_xl[(size_t)MTOT * HID];
__device__ __nv_bfloat16 g_wsh[4][(size_t)HID * HID];
__device__ __nv_bfloat16 g_wsl[4][(size_t)HID * HID];
__device__ __nv_bfloat16 g_qh[(size_t)MTOT * HID];
__device__ __nv_bfloat16 g_ql[(size_t)MTOT * HID];
__device__ __nv_bfloat16 g_kh[(size_t)MTOT * HID];
__device__ __nv_bfloat16 g_kl[(size_t)MTOT * HID];
__device__ float         g_vf[(size_t)MTOT * HID];
__device__ __nv_bfloat16 g_vth[(size_t)MTOT * HID];
__device__ __nv_bfloat16 g_vtl[(size_t)MTOT * HID];
__device__ float         g_sf[(size_t)BATCH * SEQL * SEQL];
__device__ __nv_bfloat16 g_ph_[(size_t)BATCH * SEQL * SEQL];
__device__ __nv_bfloat16 g_pl_[(size_t)BATCH * SEQL * SEQL];
__device__ __nv_bfloat16 g_oh[(size_t)MTOT * HID];
__device__ __nv_bfloat16 g_ol[(size_t)MTOT * HID];

// ---------------------------------------------------------------------------
// PTX helpers (all base-target: sm_75/sm_80 features)
// ---------------------------------------------------------------------------
__device__ __forceinline__ uint32_t smem_u32(const void* p) {
    uint32_t a;
    asm("{ .reg .u64 t; cvta.to.shared.u64 t, %1; cvt.u32.u64 %0, t; }" : "=r"(a) : "l"(p));
    return a;
}
__device__ __forceinline__ void cp16(uint32_t dst, const void* src) {
    asm volatile("cp.async.cg.shared.global [%0], [%1], 16;" :: "r"(dst), "l"(src));
}
#define CP_COMMIT() asm volatile("cp.async.commit_group;" ::: "memory")
#define CP_WAIT0()  asm volatile("cp.async.wait_group 0;" ::: "memory")

__device__ __forceinline__ void ldm_x4(uint32_t* r, uint32_t addr) {
    asm volatile("ldmatrix.sync.aligned.m8n8.x4.shared.b16 {%0,%1,%2,%3}, [%4];"
                 : "=r"(r[0]), "=r"(r[1]), "=r"(r[2]), "=r"(r[3]) : "r"(addr));
}
__device__ __forceinline__ void mma_bf16(float* d, const uint32_t* a, const uint32_t* b) {
    asm volatile(
        "mma.sync.aligned.m16n8k16.row.col.f32.bf16.bf16.f32 "
        "{%0,%1,%2,%3}, {%4,%5,%6,%7}, {%8,%9}, {%0,%1,%2,%3};"
        : "+f"(d[0]), "+f"(d[1]), "+f"(d[2]), "+f"(d[3])
        : "r"(a[0]), "r"(a[1]), "r"(a[2]), "r"(a[3]), "r"(b[0]), "r"(b[1]));
}
__device__ __forceinline__ void split2(float v, __nv_bfloat16& h, __nv_bfloat16& l) {
    h = __float2bfloat16(v);
    l = __float2bfloat16(v - __bfloat162float(h));
}
// 64B-row tile swizzle: 16B chunk kg at row -> kg ^ ((row>>1)&3). Conflict-free
// for ldmatrix 8-row groups (rows base%16==0) and for cp.async stores.
__device__ __forceinline__ uint32_t tswz(int row, int kg) {
    return (uint32_t)(row * 64 + ((kg ^ ((row >> 1) & 3)) << 4));
}

// ---------------------------------------------------------------------------
// Split-bf16 NT GEMM: C = alpha * (A @ B^T) + bias
//   A[M,K] K-major (Ah,Al); B[N,K] K-major (Bh,Bl). Output fp32 OR split bf16.
//   Batched via blockIdx.z with explicit strides.
// 256 threads, 8 warps (4 m x 2 n), warp tile 32x64, acc fp32 in registers.
// ---------------------------------------------------------------------------
__global__ __launch_bounds__(256, 2) void mmagemm(
    const __nv_bfloat16* __restrict__ Ah, const __nv_bfloat16* __restrict__ Al,
    const __nv_bfloat16* __restrict__ Bh, const __nv_bfloat16* __restrict__ Bl,
    const float* __restrict__ bias, float alpha,
    float* __restrict__ Cf,
    __nv_bfloat16* __restrict__ Ch, __nv_bfloat16* __restrict__ Cl,
    int K, int N, long long sAB, long long sBB, long long sCB)
{
    extern __shared__ char smem[];
    const uint32_t sb = smem_u32(smem);
    const int tid  = threadIdx.x;
    const int lane = tid & 31;
    const int wid  = tid >> 5;
    const int wm   = wid & 3;        // 0..3 -> m offset 32*wm
    const int wn   = wid >> 2;       // 0..1 -> n offset 64*wn
    const long long z = blockIdx.z;
    const int m0 = blockIdx.y * BM;
    const int n0 = blockIdx.x * BN;

    const __nv_bfloat16* srcs[4] = {
        Ah + z * sAB + (long long)m0 * K,
        Al + z * sAB + (long long)m0 * K,
        Bh + z * sBB + (long long)n0 * K,
        Bl + z * sBB + (long long)n0 * K };

    float acc[2][8][4];
#pragma unroll
    for (int i = 0; i < 2; i++)
#pragma unroll
        for (int j = 0; j < 8; j++)
#pragma unroll
            for (int q = 0; q < 4; q++) acc[i][j][q] = 0.0f;

    const int KC = K / BK;

    // ---- stage loader: 4 tiles x 512 16B-chunks, 8 cp.async per thread ----
    auto load_stage = [&](int s, int k0) {
        const uint32_t base = sb + s * STAGE_B;
#pragma unroll
        for (int t = 0; t < 4; t++) {
#pragma unroll
            for (int h = 0; h < 2; h++) {
                const int c = tid + h * 256;         // 0..511
                const int row = c >> 2;
                const int kg  = c & 3;
                cp16(base + t * TILE_B + tswz(row, kg),
                     srcs[t] + (long long)row * K + k0 + kg * 8);
            }
        }
        CP_COMMIT();
    };

    load_stage(0, 0);

    for (int c = 0; c < KC; ++c) {
        CP_WAIT0();
        __syncthreads();                       // stage c ready; prev compute done
        if (c + 1 < KC) load_stage((c + 1) & 1, (c + 1) * BK);

        const uint32_t st = sb + (c & 1) * STAGE_B;
#pragma unroll
        for (int ks = 0; ks < 2; ++ks) {       // two k16 steps per BK=32
            uint32_t afh[2][4], afl[2][4];
#pragma unroll
            for (int mt = 0; mt < 2; ++mt) {
                const int row = wm * 32 + mt * 16 + (lane & 15);
                const int kg  = (lane >> 4) + ks * 2;
                const uint32_t a = st + tswz(row, kg);
                ldm_x4(afh[mt], a);
                ldm_x4(afl[mt], a + TILE_B);
            }
#pragma unroll
            for (int p = 0; p < 4; ++p) {      // pairs of n8 tiles
                const int n  = wn * 64 + p * 16 + (lane & 7) + ((lane >> 4) & 1) * 8;
                const int kg = ((lane >> 3) & 1) + ks * 2;
                const uint32_t b = st + 2 * TILE_B + tswz(n, kg);
                uint32_t bfh[4], bfl[4];
                ldm_x4(bfh, b);
                ldm_x4(bfl, b + TILE_B);
#pragma unroll
                for (int mt = 0; mt < 2; ++mt) {
#pragma unroll
                    for (int s2 = 0; s2 < 2; ++s2) {
                        float* d = acc[mt][p * 2 + s2];
                        mma_bf16(d, afh[mt], bfh + s2 * 2);   // hi*hi
                        mma_bf16(d, afh[mt], bfl + s2 * 2);   // hi*lo
                        mma_bf16(d, afl[mt], bfh + s2 * 2);   // lo*hi
                    }
                }
            }
        }
    }

    // ---- epilogue ----
    const int r_base = m0 + wm * 32 + (lane >> 2);
    const int c_base = n0 + wn * 64 + (lane & 3) * 2;
#pragma unroll
    for (int mt = 0; mt < 2; ++mt) {
#pragma unroll
        for (int nt = 0; nt < 8; ++nt) {
            const int row = r_base + mt * 16;
            const int col = c_base + nt * 8;
            float v0 = acc[mt][nt][0] * alpha;
            float v1 = acc[mt][nt][1] * alpha;
            float v2 = acc[mt][nt][2] * alpha;
            float v3 = acc[mt][nt][3] * alpha;
            if (bias) {
                const float b0 = bias[col], b1 = bias[col + 1];
                v0 += b0; v1 += b1; v2 += b0; v3 += b1;
            }
            const long long o1 = z * sCB + (long long)row * N + col;
            const long long o2 = o1 + 8ll * N;
            if (Cf) {
                *(float2*)&Cf[o1] = make_float2(v0, v1);
                *(float2*)&Cf[o2] = make_float2(v2, v3);
            } else {
                __nv_bfloat16 h0, l0, h1, l1;
                split2(v0, h0, l0); split2(v1, h1, l1);
                *(__nv_bfloat162*)&Ch[o1] = __halves2bfloat162(h0, h1);
                *(__nv_bfloat162*)&Cl[o1] = __halves2bfloat162(l0, l1);
                split2(v2, h0, l0); split2(v3, h1, l1);
                *(__nv_bfloat162*)&Ch[o2] = __halves2bfloat162(h0, h1);
                *(__nv_bfloat162*)&Cl[o2] = __halves2bfloat162(l0, l1);
            }
        }
    }
}

// ---------------------------------------------------------------------------
// fp32 -> (hi, lo) bf16 split, one float4 per thread.
// ---------------------------------------------------------------------------
__global__ __launch_bounds__(256) void split4(const float* __restrict__ in,
                                              __nv_bfloat16* __restrict__ h,
                                              __nv_bfloat16* __restrict__ l)
{
    const long long i = (long long)blockIdx.x * 256 + threadIdx.x;
    float4 v = ((const float4*)in)[i];
    __nv_bfloat16 h0, l0, h1, l1, h2, l2, h3, l3;
    split2(v.x, h0, l0); split2(v.y, h1, l1);
    split2(v.z, h2, l2); split2(v.w, h3, l3);
    ((__nv_bfloat162*)h)[2 * i + 0] = __halves2bfloat162(h0, h1);
    ((__nv_bfloat162*)h)[2 * i + 1] = __halves2bfloat162(h2, h3);
    ((__nv_bfloat162*)l)[2 * i + 0] = __halves2bfloat162(l0, l1);
    ((__nv_bfloat162*)l)[2 * i + 1] = __halves2bfloat162(l2, l3);
}

// ---------------------------------------------------------------------------
// Batched transpose + split: V[b][s][h] fp32 -> Vt hi/lo [b][h][s] bf16.
// ---------------------------------------------------------------------------
__global__ __launch_bounds__(256) void transpose_split(const float* __restrict__ V,
                                                       __nv_bfloat16* __restrict__ Th,
                                                       __nv_bfloat16* __restrict__ Tl)
{
    __shared__ float t[32][33];
    const int b = blockIdx.z;
    const float* Vb = V + (size_t)b * SEQL * HID;
    __nv_bfloat16* Thb = Th + (size_t)b * HID * SEQL;
    __nv_bfloat16* Tlb = Tl + (size_t)b * HID * SEQL;
    const int h0 = blockIdx.x * 32;
    const int s0 = blockIdx.y * 32;
    const int tx = threadIdx.x & 31;
    const int ty = threadIdx.x >> 5;
#pragma unroll
    for (int j = 0; j < 4; ++j)
        t[ty + 8 * j][tx] = Vb[(size_t)(s0 + ty + 8 * j) * HID + h0 + tx];
    __syncthreads();
#pragma unroll
    for (int j = 0; j < 4; ++j) {
        const float v = t[tx][ty + 8 * j];
        __nv_bfloat16 h, l;
        split2(v, h, l);
        const size_t o = (size_t)(h0 + ty + 8 * j) * SEQL + s0 + tx;
        Thb[o] = h;
        Tlb[o] = l;
    }
}

// ---------------------------------------------------------------------------
// Row softmax over fp32 scores, emitting split-bf16 weights.
// ---------------------------------------------------------------------------
__global__ __launch_bounds__(256) void softmax_split(const float* __restrict__ S,
                                                     __nv_bfloat16* __restrict__ Wh,
                                                     __nv_bfloat16* __restrict__ Wl)
{
    const float* row = S + (size_t)blockIdx.x * SEQL;
    __nv_bfloat16* rh = Wh + (size_t)blockIdx.x * SEQL;
    __nv_bfloat16* rl = Wl + (size_t)blockIdx.x * SEQL;
    const int tid = threadIdx.x;
    __shared__ float red[256];

    float vals[16];
    float lmax = -3.402823e38f;
#pragma unroll
    for (int i = 0; i < 4; ++i) {
        float4 t = *(const float4*)&row[(tid + i * 256) * 4];
        vals[i * 4 + 0] = t.x; vals[i * 4 + 1] = t.y;
        vals[i * 4 + 2] = t.z; vals[i * 4 + 3] = t.w;
        lmax = fmaxf(lmax, fmaxf(fmaxf(t.x, t.y), fmaxf(t.z, t.w)));
    }
    red[tid] = lmax;
    __syncthreads();
#pragma unroll
    for (int s = 128; s > 0; s >>= 1) {
        if (tid < s) red[tid] = fmaxf(red[tid], red[tid + s]);
        __syncthreads();
    }
    const float m = red[0];
    __syncthreads();

    float lsum = 0.0f;
#pragma unroll
    for (int i = 0; i < 16; ++i) { vals[i] = expf(vals[i] - m); lsum += vals[i]; }
    red[tid] = lsum;
    __syncthreads();
#pragma unroll
    for (int s = 128; s > 0; s >>= 1) {
        if (tid < s) red[tid] += red[tid + s];
        __syncthreads();
    }
    const float inv = 1.0f / red[0];

#pragma unroll
    for (int i = 0; i < 4; ++i) {
        const int idx = (tid + i * 256) * 4;
        __nv_bfloat16 h0, l0, h1, l1, h2, l2, h3, l3;
        split2(vals[i * 4 + 0] * inv, h0, l0);
        split2(vals[i * 4 + 1] * inv, h1, l1);
        split2(vals[i * 4 + 2] * inv, h2, l2);
        split2(vals[i * 4 + 3] * inv, h3, l3);
        *(__nv_bfloat162*)&rh[idx + 0] = __halves2bfloat162(h0, h1);
        *(__nv_bfloat162*)&rh[idx + 2] = __halves2bfloat162(h2, h3);
        *(__nv_bfloat162*)&rl[idx + 0] = __halves2bfloat162(l0, l1);
        *(__nv_bfloat162*)&rl[idx + 2] = __halves2bfloat162(l2, l3);
    }
}

// ---------------------------------------------------------------------------
extern "C" void kernel_launch(void* const* d_in, const int* in_sizes, int n_in,
                              void* d_out, int out_size)
{
    (void)in_sizes; (void)n_in; (void)out_size;
    const float* x  = (const float*)d_in[0];
    const float* Wq = (const float*)d_in[1];
    const float* bq = (const float*)d_in[2];
    const float* Wk = (const float*)d_in[3];
    const float* bk = (const float*)d_in[4];
    const float* Wv = (const float*)d_in[5];
    const float* bv = (const float*)d_in[6];
    const float* Wo = (const float*)d_in[7];
    const float* bo = (const float*)d_in[8];
    float* out = (float*)d_out;

    __nv_bfloat16 *xh, *xl, *qh, *ql, *kh, *kl, *vth, *vtl, *ph, *pl, *oh, *ol;
    __nv_bfloat16 *wsh, *wsl;
    float *vf, *sf;
    cudaGetSymbolAddress((void**)&xh, g_xh);   cudaGetSymbolAddress((void**)&xl, g_xl);
    cudaGetSymbolAddress((void**)&wsh, g_wsh); cudaGetSymbolAddress((void**)&wsl, g_wsl);
    cudaGetSymbolAddress((void**)&qh, g_qh);   cudaGetSymbolAddress((void**)&ql, g_ql);
    cudaGetSymbolAddress((void**)&kh, g_kh);   cudaGetSymbolAddress((void**)&kl, g_kl);
    cudaGetSymbolAddress((void**)&vf, g_vf);
    cudaGetSymbolAddress((void**)&vth, g_vth); cudaGetSymbolAddress((void**)&vtl, g_vtl);
    cudaGetSymbolAddress((void**)&sf, g_sf);
    cudaGetSymbolAddress((void**)&ph, g_ph_);  cudaGetSymbolAddress((void**)&pl, g_pl_);
    cudaGetSymbolAddress((void**)&oh, g_oh);   cudaGetSymbolAddress((void**)&ol, g_ol);

    cudaFuncSetAttribute(mmagemm, cudaFuncAttributeMaxDynamicSharedMemorySize, SMEM_TOTAL);

    const size_t WELE = (size_t)HID * HID;
    const long long sQKV = (long long)SEQL * HID;
    const long long sS   = (long long)SEQL * SEQL;
    const float scl = 0.04419417382415922f;   // 1/sqrt(512)

    // ---- split inputs into hi/lo bf16 ----
    split4<<<(MTOT * (size_t)HID) / 4 / 256, 256>>>(x, xh, xl);
    split4<<<WELE / 4 / 256, 256>>>(Wq, wsh + 0 * WELE, wsl + 0 * WELE);
    split4<<<WELE / 4 / 256, 256>>>(Wk, wsh + 1 * WELE, wsl + 1 * WELE);
    split4<<<WELE / 4 / 256, 256>>>(Wv, wsh + 2 * WELE, wsl + 2 * WELE);
    split4<<<WELE / 4 / 256, 256>>>(Wo, wsh + 3 * WELE, wsl + 3 * WELE);

    // ---- projections ----
    dim3 gProj(HID / BN, MTOT / BM, 1);
    mmagemm<<<gProj, 256, SMEM_TOTAL>>>(xh, xl, wsh + 0 * WELE, wsl + 0 * WELE, bq, 1.0f,
                                        nullptr, qh, ql, HID, HID, 0, 0, 0);
    mmagemm<<<gProj, 256, SMEM_TOTAL>>>(xh, xl, wsh + 1 * WELE, wsl + 1 * WELE, bk, 1.0f,
                                        nullptr, kh, kl, HID, HID, 0, 0, 0);
    mmagemm<<<gProj, 256, SMEM_TOTAL>>>(xh, xl, wsh + 2 * WELE, wsl + 2 * WELE, bv, 1.0f,
                                        vf, nullptr, nullptr, HID, HID, 0, 0, 0);

    // ---- V transpose + split ----
    transpose_split<<<dim3(HID / 32, SEQL / 32, BATCH), 256>>>(vf, vth, vtl);

    // ---- scores = Q K^T / sqrt(512) ----
    mmagemm<<<dim3(SEQL / BN, SEQL / BM, BATCH), 256, SMEM_TOTAL>>>(
        qh, ql, kh, kl, nullptr, scl, sf, nullptr, nullptr,
        HID, SEQL, sQKV, sQKV, sS);

    // ---- softmax -> split weights ----
    softmax_split<<<BATCH * SEQL, 256>>>(sf, ph, pl);

    // ---- O = weights @ V  (B operand = V^T, K-major over seq) ----
    mmagemm<<<dim3(HID / BN, SEQL / BM, BATCH), 256, SMEM_TOTAL>>>(
        ph, pl, vth, vtl, nullptr, 1.0f, nullptr, oh, ol,
        SEQL, HID, sS, sQKV, sQKV);

    // ---- out = O @ Wo^T + bo ----
    mmagemm<<<gProj, 256, SMEM_TOTAL>>>(oh, ol, wsh + 3 * WELE, wsl + 3 * WELE, bo, 1.0f,
                                        out, nullptr, nullptr, HID, HID, 0, 0, 0);
}

// round 10
// speedup vs baseline: 4.7636x; 1.3949x over previous
#include <cuda_runtime.h>
#include <cuda_fp16.h>
#include <stdint.h>
#include <math.h>

// ---------------------------------------------------------------------------
// WaveInterference via warp-level fp16 mma.sync, 2-pass split GEMM:
//   C = A_hi * (B_hi + B_lo), A stored hi-only fp16, B split hi/lo fp16.
// Weights pre-scaled x32 so B_lo stays in fp16 normal range (alpha undoes it).
// B=4, S=4096, H=1024.
// ---------------------------------------------------------------------------

#define BATCH 4
#define SEQL  4096
#define HID   1024
#define MTOT  (BATCH * SEQL)   // 16384

#define BM 128
#define BN 128
#define BK 32
#define TILE_B   8192              // 128 rows x 64 B (32 fp16)
#define STAGE_B  (3 * TILE_B)      // Ah, Bh, Bl
#define NSTAGE   3
#define SMEM_TOTAL (NSTAGE * STAGE_B)   // 73728 B; x2 CTAs = 147456 <= 228KB

#define WSCALE     32.0f
#define INV_WSCALE 0.03125f

// ---------------------------------------------------------------------------
// Device scratch (no allocs allowed anywhere).
// ---------------------------------------------------------------------------
__device__ __half g_xh[(size_t)MTOT * HID];
__device__ __half g_wh[4][(size_t)HID * HID];     // Wq,Wk,Wv,Wo hi (x32)
__device__ __half g_wl[4][(size_t)HID * HID];     // lo (x32)
__device__ float  g_bias3[3 * HID];               // bq|bk|bv concat
__device__ __half g_qkh[2][(size_t)MTOT * HID];   // Q hi, K hi
__device__ __half g_kl[(size_t)MTOT * HID];       // K lo
__device__ float  g_vf[(size_t)MTOT * HID];       // V fp32 (pre-transpose)
__device__ __half g_vth[(size_t)MTOT * HID];      // V^T hi
__device__ __half g_vtl[(size_t)MTOT * HID];      // V^T lo
__device__ float  g_sf[(size_t)BATCH * SEQL * SEQL];   // scores fp32
__device__ __half g_ph_[(size_t)BATCH * SEQL * SEQL];  // softmax weights hi
__device__ __half g_oh[(size_t)MTOT * HID];       // attention out hi

// ---------------------------------------------------------------------------
// PTX helpers (base-target sm_75/sm_80 features only)
// ---------------------------------------------------------------------------
__device__ __forceinline__ uint32_t smem_u32(const void* p) {
    uint32_t a;
    asm("{ .reg .u64 t; cvta.to.shared.u64 t, %1; cvt.u32.u64 %0, t; }" : "=r"(a) : "l"(p));
    return a;
}
__device__ __forceinline__ void cp16(uint32_t dst, const void* src) {
    asm volatile("cp.async.cg.shared.global [%0], [%1], 16;" :: "r"(dst), "l"(src));
}
#define CP_COMMIT() asm volatile("cp.async.commit_group;" ::: "memory")
#define CP_WAIT0()  asm volatile("cp.async.wait_group 0;" ::: "memory")
#define CP_WAIT1()  asm volatile("cp.async.wait_group 1;" ::: "memory")

__device__ __forceinline__ void ldm_x4(uint32_t* r, uint32_t addr) {
    asm volatile("ldmatrix.sync.aligned.m8n8.x4.shared.b16 {%0,%1,%2,%3}, [%4];"
                 : "=r"(r[0]), "=r"(r[1]), "=r"(r[2]), "=r"(r[3]) : "r"(addr));
}
__device__ __forceinline__ void mma_fp16(float* d, const uint32_t* a, const uint32_t* b) {
    asm volatile(
        "mma.sync.aligned.m16n8k16.row.col.f32.f16.f16.f32 "
        "{%0,%1,%2,%3}, {%4,%5,%6,%7}, {%8,%9}, {%0,%1,%2,%3};"
        : "+f"(d[0]), "+f"(d[1]), "+f"(d[2]), "+f"(d[3])
        : "r"(a[0]), "r"(a[1]), "r"(a[2]), "r"(a[3]), "r"(b[0]), "r"(b[1]));
}
__device__ __forceinline__ void split2h(float v, __half& h, __half& l) {
    h = __float2half_rn(v);
    l = __float2half_rn(v - __half2float(h));
}
// 64B-row tile swizzle (conflict-free for cp.async stores + ldmatrix reads).
__device__ __forceinline__ uint32_t tswz(int row, int kg) {
    return (uint32_t)(row * 64 + ((kg ^ ((row >> 1) & 3)) << 4));
}

// ---------------------------------------------------------------------------
// 2-pass split-fp16 NT GEMM: C = alpha * (A @ (Bh+Bl)^T) + bias
//   A[M,K] K-major fp16 hi; B[N,K] K-major fp16 hi+lo. 3-stage cp.async pipe.
//   Per-z output mode: fp32 (f32mask) / fp16-hi (+lo plane if lomask).
// 256 threads, 8 warps (4m x 2n), warp tile 32x64, fp32 register accumulators.
// ---------------------------------------------------------------------------
__global__ __launch_bounds__(256, 2) void mmagemm(
    const __half* __restrict__ Ah,
    const __half* __restrict__ Bh, const __half* __restrict__ Bl,
    const float* __restrict__ bias, int biasStride, float alpha,
    float* __restrict__ Cf, __half* __restrict__ Ch, __half* __restrict__ Cl,
    int K, int N, long long sAB, long long sBB,
    long long sCH, long long sCF, int f32mask, int lomask)
{
    extern __shared__ char smem[];
    const uint32_t sb = smem_u32(smem);
    const int tid  = threadIdx.x;
    const int lane = tid & 31;
    const int wid  = tid >> 5;
    const int wm   = wid & 3;
    const int wn   = wid >> 2;
    const int z    = blockIdx.z;
    const int m0   = blockIdx.y * BM;
    const int n0   = blockIdx.x * BN;
    const bool wF32 = (f32mask >> z) & 1;
    const bool wLo  = (lomask >> z) & 1;

    const __half* srcs[3] = {
        Ah + (long long)z * sAB + (long long)m0 * K,
        Bh + (long long)z * sBB + (long long)n0 * K,
        Bl + (long long)z * sBB + (long long)n0 * K };

    float acc[2][8][4];
#pragma unroll
    for (int i = 0; i < 2; i++)
#pragma unroll
        for (int j = 0; j < 8; j++)
#pragma unroll
            for (int q = 0; q < 4; q++) acc[i][j][q] = 0.0f;

    const int KC = K / BK;

    auto load_stage = [&](int s, int k0) {
        const uint32_t base = sb + s * STAGE_B;
#pragma unroll
        for (int t = 0; t < 3; t++) {
#pragma unroll
            for (int h = 0; h < 2; h++) {
                const int c = tid + h * 256;     // 0..511
                const int row = c >> 2;
                const int kg  = c & 3;
                cp16(base + t * TILE_B + tswz(row, kg),
                     srcs[t] + (long long)row * K + k0 + kg * 8);
            }
        }
        CP_COMMIT();
    };

    load_stage(0, 0);
    load_stage(1, BK);

    for (int c = 0; c < KC; ++c) {
        if (c == KC - 1) CP_WAIT0(); else CP_WAIT1();
        __syncthreads();                 // stage c ready; compute c-1 done
        if (c + 2 < KC) {
            int s2i = c + 2;
            load_stage(s2i % NSTAGE, s2i * BK);
        }

        const uint32_t st = sb + (c % NSTAGE) * STAGE_B;
#pragma unroll
        for (int ks = 0; ks < 2; ++ks) {
            uint32_t afh[2][4];
#pragma unroll
            for (int mt = 0; mt < 2; ++mt) {
                const int row = wm * 32 + mt * 16 + (lane & 15);
                const int kg  = (lane >> 4) + ks * 2;
                ldm_x4(afh[mt], st + tswz(row, kg));
            }
#pragma unroll
            for (int p = 0; p < 4; ++p) {
                const int n  = wn * 64 + p * 16 + (lane & 7) + ((lane >> 4) & 1) * 8;
                const int kg = ((lane >> 3) & 1) + ks * 2;
                uint32_t bfh[4], bfl[4];
                ldm_x4(bfh, st + TILE_B + tswz(n, kg));
                ldm_x4(bfl, st + 2 * TILE_B + tswz(n, kg));
#pragma unroll
                for (int mt = 0; mt < 2; ++mt) {
#pragma unroll
                    for (int s2 = 0; s2 < 2; ++s2) {
                        float* d = acc[mt][p * 2 + s2];
                        mma_fp16(d, afh[mt], bfh + s2 * 2);   // hi*hi
                        mma_fp16(d, afh[mt], bfl + s2 * 2);   // hi*lo
                    }
                }
            }
        }
    }

    // ---- epilogue ----
    const int r_base = m0 + wm * 32 + (lane >> 2);
    const int c_base = n0 + wn * 64 + (lane & 3) * 2;
#pragma unroll
    for (int mt = 0; mt < 2; ++mt) {
#pragma unroll
        for (int nt = 0; nt < 8; ++nt) {
            const int row = r_base + mt * 16;
            const int col = c_base + nt * 8;
            float v0 = acc[mt][nt][0] * alpha;
            float v1 = acc[mt][nt][1] * alpha;
            float v2 = acc[mt][nt][2] * alpha;
            float v3 = acc[mt][nt][3] * alpha;
            if (bias) {
                const float b0 = bias[z * biasStride + col];
                const float b1 = bias[z * biasStride + col + 1];
                v0 += b0; v1 += b1; v2 += b0; v3 += b1;
            }
            const long long co1 = (long long)row * N + col;
            const long long co2 = co1 + 8ll * N;
            if (wF32) {
                *(float2*)&Cf[z * sCF + co1] = make_float2(v0, v1);
                *(float2*)&Cf[z * sCF + co2] = make_float2(v2, v3);
            } else {
                *(__half2*)&Ch[z * sCH + co1] =
                    __halves2half2(__float2half_rn(v0), __float2half_rn(v1));
                *(__half2*)&Ch[z * sCH + co2] =
                    __halves2half2(__float2half_rn(v2), __float2half_rn(v3));
                if (wLo) {
                    __half h, l0, l1;
                    split2h(v0, h, l0); split2h(v1, h, l1);
                    *(__half2*)&Cl[co1] = __halves2half2(l0, l1);
                    split2h(v2, h, l0); split2h(v3, h, l1);
                    *(__half2*)&Cl[co2] = __halves2half2(l0, l1);
                }
            }
        }
    }
}

// ---------------------------------------------------------------------------
// x -> fp16 hi only (one float4 per thread).
// ---------------------------------------------------------------------------
__global__ __launch_bounds__(256) void splitX(const float* __restrict__ in,
                                              __half* __restrict__ h)
{
    const long long i = (long long)blockIdx.x * 256 + threadIdx.x;
    float4 v = ((const float4*)in)[i];
    ((__half2*)h)[2 * i + 0] = __halves2half2(__float2half_rn(v.x), __float2half_rn(v.y));
    ((__half2*)h)[2 * i + 1] = __halves2half2(__float2half_rn(v.z), __float2half_rn(v.w));
}

// ---------------------------------------------------------------------------
// W -> (hi, lo) fp16 at x32 scale.
// ---------------------------------------------------------------------------
__global__ __launch_bounds__(256) void splitW(const float* __restrict__ in,
                                              __half* __restrict__ h,
                                              __half* __restrict__ l)
{
    const long long i = (long long)blockIdx.x * 256 + threadIdx.x;
    float4 v = ((const float4*)in)[i];
    __half h0, l0, h1, l1, h2, l2, h3, l3;
    split2h(v.x * WSCALE, h0, l0); split2h(v.y * WSCALE, h1, l1);
    split2h(v.z * WSCALE, h2, l2); split2h(v.w * WSCALE, h3, l3);
    ((__half2*)h)[2 * i + 0] = __halves2half2(h0, h1);
    ((__half2*)h)[2 * i + 1] = __halves2half2(h2, h3);
    ((__half2*)l)[2 * i + 0] = __halves2half2(l0, l1);
    ((__half2*)l)[2 * i + 1] = __halves2half2(l2, l3);
}

__global__ void concat_bias(const float* __restrict__ bq, const float* __restrict__ bk,
                            const float* __restrict__ bv, float* __restrict__ dst)
{
    const int i = blockIdx.x * 256 + threadIdx.x;
    if (i < HID)            dst[i] = bq[i];
    else if (i < 2 * HID)   dst[i] = bk[i - HID];
    else if (i < 3 * HID)   dst[i] = bv[i - 2 * HID];
}

// ---------------------------------------------------------------------------
// Batched transpose + split: V[b][s][h] fp32 -> Vt hi/lo [b][h][s] fp16.
// ---------------------------------------------------------------------------
__global__ __launch_bounds__(256) void transpose_split(const float* __restrict__ V,
                                                       __half* __restrict__ Th,
                                                       __half* __restrict__ Tl)
{
    __shared__ float t[32][33];
    const int b = blockIdx.z;
    const float* Vb = V + (size_t)b * SEQL * HID;
    __half* Thb = Th + (size_t)b * HID * SEQL;
    __half* Tlb = Tl + (size_t)b * HID * SEQL;
    const int h0 = blockIdx.x * 32;
    const int s0 = blockIdx.y * 32;
    const int tx = threadIdx.x & 31;
    const int ty = threadIdx.x >> 5;
#pragma unroll
    for (int j = 0; j < 4; ++j)
        t[ty + 8 * j][tx] = Vb[(size_t)(s0 + ty + 8 * j) * HID + h0 + tx];
    __syncthreads();
#pragma unroll
    for (int j = 0; j < 4; ++j) {
        const float v = t[tx][ty + 8 * j];
        __half h, l;
        split2h(v, h, l);
        const size_t o = (size_t)(h0 + ty + 8 * j) * SEQL + s0 + tx;
        Thb[o] = h;
        Tlb[o] = l;
    }
}

// ---------------------------------------------------------------------------
// Row softmax over fp32 scores -> fp16 hi weights.
// ---------------------------------------------------------------------------
__global__ __launch_bounds__(256) void softmax_h(const float* __restrict__ S,
                                                 __half* __restrict__ Wh)
{
    const float* row = S + (size_t)blockIdx.x * SEQL;
    __half* rh = Wh + (size_t)blockIdx.x * SEQL;
    const int tid = threadIdx.x;
    __shared__ float red[256];

    float vals[16];
    float lmax = -3.402823e38f;
#pragma unroll
    for (int i = 0; i < 4; ++i) {
        float4 t = *(const float4*)&row[(tid + i * 256) * 4];
        vals[i * 4 + 0] = t.x; vals[i * 4 + 1] = t.y;
        vals[i * 4 + 2] = t.z; vals[i * 4 + 3] = t.w;
        lmax = fmaxf(lmax, fmaxf(fmaxf(t.x, t.y), fmaxf(t.z, t.w)));
    }
    red[tid] = lmax;
    __syncthreads();
#pragma unroll
    for (int s = 128; s > 0; s >>= 1) {
        if (tid < s) red[tid] = fmaxf(red[tid], red[tid + s]);
        __syncthreads();
    }
    const float m = red[0];
    __syncthreads();

    float lsum = 0.0f;
#pragma unroll
    for (int i = 0; i < 16; ++i) { vals[i] = expf(vals[i] - m); lsum += vals[i]; }
    red[tid] = lsum;
    __syncthreads();
#pragma unroll
    for (int s = 128; s > 0; s >>= 1) {
        if (tid < s) red[tid] += red[tid + s];
        __syncthreads();
    }
    const float inv = 1.0f / red[0];

#pragma unroll
    for (int i = 0; i < 4; ++i) {
        const int idx = (tid + i * 256) * 4;
        *(__half2*)&rh[idx + 0] = __halves2half2(
            __float2half_rn(vals[i * 4 + 0] * inv), __float2half_rn(vals[i * 4 + 1] * inv));
        *(__half2*)&rh[idx + 2] = __halves2half2(
            __float2half_rn(vals[i * 4 + 2] * inv), __float2half_rn(vals[i * 4 + 3] * inv));
    }
}

// ---------------------------------------------------------------------------
extern "C" void kernel_launch(void* const* d_in, const int* in_sizes, int n_in,
                              void* d_out, int out_size)
{
    (void)in_sizes; (void)n_in; (void)out_size;
    const float* x  = (const float*)d_in[0];
    const float* Wq = (const float*)d_in[1];
    const float* bq = (const float*)d_in[2];
    const float* Wk = (const float*)d_in[3];
    const float* bk = (const float*)d_in[4];
    const float* Wv = (const float*)d_in[5];
    const float* bv = (const float*)d_in[6];
    const float* Wo = (const float*)d_in[7];
    const float* bo = (const float*)d_in[8];
    float* out = (float*)d_out;

    __half *xh, *wh, *wl, *qkh, *kl, *vth, *vtl, *ph, *oh;
    float *vf, *sf, *bias3;
    cudaGetSymbolAddress((void**)&xh, g_xh);
    cudaGetSymbolAddress((void**)&wh, g_wh);   cudaGetSymbolAddress((void**)&wl, g_wl);
    cudaGetSymbolAddress((void**)&bias3, g_bias3);
    cudaGetSymbolAddress((void**)&qkh, g_qkh); cudaGetSymbolAddress((void**)&kl, g_kl);
    cudaGetSymbolAddress((void**)&vf, g_vf);
    cudaGetSymbolAddress((void**)&vth, g_vth); cudaGetSymbolAddress((void**)&vtl, g_vtl);
    cudaGetSymbolAddress((void**)&sf, g_sf);
    cudaGetSymbolAddress((void**)&ph, g_ph_);
    cudaGetSymbolAddress((void**)&oh, g_oh);

    cudaFuncSetAttribute(mmagemm, cudaFuncAttributeMaxDynamicSharedMemorySize, SMEM_TOTAL);

    const size_t WELE = (size_t)HID * HID;
    const long long sQKV = (long long)SEQL * HID;
    const long long sS   = (long long)SEQL * SEQL;
    const long long sPL  = (long long)MTOT * HID;   // plane stride
    const float scl = 0.04419417382415922f;         // 1/sqrt(512)

    // ---- input conversions ----
    splitX<<<(MTOT * (size_t)HID) / 4 / 256, 256>>>(x, xh);
    splitW<<<WELE / 4 / 256, 256>>>(Wq, wh + 0 * WELE, wl + 0 * WELE);
    splitW<<<WELE / 4 / 256, 256>>>(Wk, wh + 1 * WELE, wl + 1 * WELE);
    splitW<<<WELE / 4 / 256, 256>>>(Wv, wh + 2 * WELE, wl + 2 * WELE);
    splitW<<<WELE / 4 / 256, 256>>>(Wo, wh + 3 * WELE, wl + 3 * WELE);
    concat_bias<<<(3 * HID + 255) / 256, 256>>>(bq, bk, bv, bias3);

    // ---- merged QKV projection: z=0 -> Q hi, z=1 -> K hi+lo, z=2 -> V fp32 ----
    mmagemm<<<dim3(HID / BN, MTOT / BM, 3), 256, SMEM_TOTAL>>>(
        xh, wh, wl, bias3, HID, INV_WSCALE,
        vf, qkh, kl,
        HID, HID, /*sAB*/0, /*sBB*/(long long)WELE,
        /*sCH*/sPL, /*sCF*/0, /*f32mask*/0b100, /*lomask*/0b010);

    // ---- V transpose + split ----
    transpose_split<<<dim3(HID / 32, SEQL / 32, BATCH), 256>>>(vf, vth, vtl);

    // ---- scores = Q K^T / sqrt(512) (fp32 out, per-batch z) ----
    mmagemm<<<dim3(SEQL / BN, SEQL / BM, BATCH), 256, SMEM_TOTAL>>>(
        qkh, qkh + sPL, kl, nullptr, 0, scl,
        sf, nullptr, nullptr,
        HID, SEQL, sQKV, sQKV, 0, sS, 0xF, 0);

    // ---- softmax -> fp16 hi weights ----
    softmax_h<<<BATCH * SEQL, 256>>>(sf, ph);

    // ---- O = weights @ V (B = V^T hi+lo), fp16 hi out ----
    mmagemm<<<dim3(HID / BN, SEQL / BM, BATCH), 256, SMEM_TOTAL>>>(
        ph, vth, vtl, nullptr, 0, 1.0f,
        nullptr, oh, nullptr,
        SEQL, HID, sS, sQKV, sQKV, 0, 0, 0);

    // ---- out = O @ Wo^T + bo (fp32 out) ----
    mmagemm<<<dim3(HID / BN, MTOT / BM, 1), 256, SMEM_TOTAL>>>(
        oh, wh + 3 * WELE, wl + 3 * WELE, bo, 0, INV_WSCALE,
        out, nullptr, nullptr,
        HID, HID, 0, 0, 0, 0, 1, 0);
}

// round 11
// speedup vs baseline: 5.5600x; 1.1672x over previous
#include <cuda_runtime.h>
#include <cuda_fp16.h>
#include <stdint.h>
#include <math.h>

// ---------------------------------------------------------------------------
// WaveInterference via warp-level fp16 mma.sync split GEMMs.
//   Projections / scores / out-proj: C = A_hi * (B_hi + B_lo)  (2-pass)
//   P*V:                            C = A_hi * B_hi            (1-pass)
// Weights pre-scaled x32 so B_lo stays fp16-normal (alpha undoes it).
// B=4, S=4096, H=1024.
// ---------------------------------------------------------------------------

#define BATCH 4
#define SEQL  4096
#define HID   1024
#define MTOT  (BATCH * SEQL)   // 16384

#define BM 128
#define BN 128
#define BK 32
#define TILE_B   8192              // 128 rows x 64 B (32 fp16)
#define NSTAGE   3

#define WSCALE     32.0f
#define INV_WSCALE 0.03125f

// ---------------------------------------------------------------------------
// Device scratch (no allocs allowed anywhere).
// ---------------------------------------------------------------------------
__device__ __half g_xh[(size_t)MTOT * HID];
__device__ __half g_wh[4][(size_t)HID * HID];     // Wq,Wk,Wv,Wo hi (x32)
__device__ __half g_wl[4][(size_t)HID * HID];     // lo (x32)
__device__ float  g_bias3[3 * HID];               // bq|bk|bv concat
__device__ __half g_qkh[2][(size_t)MTOT * HID];   // Q hi, K hi
__device__ __half g_kl[(size_t)MTOT * HID];       // K lo
__device__ float  g_vf[(size_t)MTOT * HID];       // V fp32 (pre-transpose)
__device__ __half g_vth[(size_t)MTOT * HID];      // V^T hi
__device__ float  g_sf[(size_t)BATCH * SEQL * SEQL];   // scores fp32
__device__ __half g_ph_[(size_t)BATCH * SEQL * SEQL];  // softmax weights hi
__device__ __half g_oh[(size_t)MTOT * HID];       // attention out hi

// ---------------------------------------------------------------------------
// PTX helpers (base-target sm_75/sm_80 features only)
// ---------------------------------------------------------------------------
__device__ __forceinline__ uint32_t smem_u32(const void* p) {
    uint32_t a;
    asm("{ .reg .u64 t; cvta.to.shared.u64 t, %1; cvt.u32.u64 %0, t; }" : "=r"(a) : "l"(p));
    return a;
}
__device__ __forceinline__ void cp16(uint32_t dst, const void* src) {
    asm volatile("cp.async.cg.shared.global [%0], [%1], 16;" :: "r"(dst), "l"(src));
}
#define CP_COMMIT() asm volatile("cp.async.commit_group;" ::: "memory")
#define CP_WAIT0()  asm volatile("cp.async.wait_group 0;" ::: "memory")
#define CP_WAIT1()  asm volatile("cp.async.wait_group 1;" ::: "memory")

__device__ __forceinline__ void ldm_x4(uint32_t* r, uint32_t addr) {
    asm volatile("ldmatrix.sync.aligned.m8n8.x4.shared.b16 {%0,%1,%2,%3}, [%4];"
                 : "=r"(r[0]), "=r"(r[1]), "=r"(r[2]), "=r"(r[3]) : "r"(addr));
}
__device__ __forceinline__ void mma_fp16(float* d, const uint32_t* a, const uint32_t* b) {
    asm volatile(
        "mma.sync.aligned.m16n8k16.row.col.f32.f16.f16.f32 "
        "{%0,%1,%2,%3}, {%4,%5,%6,%7}, {%8,%9}, {%0,%1,%2,%3};"
        : "+f"(d[0]), "+f"(d[1]), "+f"(d[2]), "+f"(d[3])
        : "r"(a[0]), "r"(a[1]), "r"(a[2]), "r"(a[3]), "r"(b[0]), "r"(b[1]));
}
__device__ __forceinline__ void split2h(float v, __half& h, __half& l) {
    h = __float2half_rn(v);
    l = __float2half_rn(v - __half2float(h));
}
// 64B-row tile swizzle (conflict-free for cp.async stores + ldmatrix reads).
__device__ __forceinline__ uint32_t tswz(int row, int kg) {
    return (uint32_t)(row * 64 + ((kg ^ ((row >> 1) & 3)) << 4));
}

// ---------------------------------------------------------------------------
// Split-fp16 NT GEMM, NB = B planes (2: hi+lo, 1: hi only).
//   C = alpha * (A_hi @ (Bh[+Bl])^T) + bias
//   A[M,K] K-major fp16 hi; B[N,K] K-major. 3-stage cp.async pipeline.
//   Per-z output mode: fp32 (f32mask) / fp16-hi (+lo plane if lomask).
// 256 threads, 8 warps (4m x 2n), warp tile 32x64, fp32 register accumulators.
// ---------------------------------------------------------------------------
template <int NB>
__global__ __launch_bounds__(256, 2) void mmagemm(
    const __half* __restrict__ Ah,
    const __half* __restrict__ Bh, const __half* __restrict__ Bl,
    const float* __restrict__ bias, int biasStride, float alpha,
    float* __restrict__ Cf, __half* __restrict__ Ch, __half* __restrict__ Cl,
    int K, int N, long long sAB, long long sBB,
    long long sCH, long long sCF, int f32mask, int lomask)
{
    constexpr int NT      = 1 + NB;            // tiles per stage
    constexpr int STAGE_B = NT * TILE_B;

    extern __shared__ char smem[];
    const uint32_t sb = smem_u32(smem);
    const int tid  = threadIdx.x;
    const int lane = tid & 31;
    const int wid  = tid >> 5;
    const int wm   = wid & 3;
    const int wn   = wid >> 2;
    const int z    = blockIdx.z;
    const int m0   = blockIdx.y * BM;
    const int n0   = blockIdx.x * BN;
    const bool wF32 = (f32mask >> z) & 1;
    const bool wLo  = (lomask >> z) & 1;

    const __half* srcs[NT];
    srcs[0] = Ah + (long long)z * sAB + (long long)m0 * K;
    srcs[1] = Bh + (long long)z * sBB + (long long)n0 * K;
    if (NB == 2) srcs[2] = Bl + (long long)z * sBB + (long long)n0 * K;

    float acc[2][8][4];
#pragma unroll
    for (int i = 0; i < 2; i++)
#pragma unroll
        for (int j = 0; j < 8; j++)
#pragma unroll
            for (int q = 0; q < 4; q++) acc[i][j][q] = 0.0f;

    const int KC = K / BK;

    auto load_stage = [&](int s, int k0) {
        const uint32_t base = sb + s * STAGE_B;
#pragma unroll
        for (int t = 0; t < NT; t++) {
#pragma unroll
            for (int h = 0; h < 2; h++) {
                const int c = tid + h * 256;     // 0..511
                const int row = c >> 2;
                const int kg  = c & 3;
                cp16(base + t * TILE_B + tswz(row, kg),
                     srcs[t] + (long long)row * K + k0 + kg * 8);
            }
        }
        CP_COMMIT();
    };

    load_stage(0, 0);
    load_stage(1, BK);

    for (int c = 0; c < KC; ++c) {
        if (c == KC - 1) CP_WAIT0(); else CP_WAIT1();
        __syncthreads();                 // stage c ready; compute c-1 done
        if (c + 2 < KC) {
            const int s2i = c + 2;
            load_stage(s2i % NSTAGE, s2i * BK);
        }

        const uint32_t st = sb + (c % NSTAGE) * STAGE_B;
#pragma unroll
        for (int ks = 0; ks < 2; ++ks) {
            uint32_t afh[2][4];
#pragma unroll
            for (int mt = 0; mt < 2; ++mt) {
                const int row = wm * 32 + mt * 16 + (lane & 15);
                const int kg  = (lane >> 4) + ks * 2;
                ldm_x4(afh[mt], st + tswz(row, kg));
            }
#pragma unroll
            for (int p = 0; p < 4; ++p) {
                const int n  = wn * 64 + p * 16 + (lane & 7) + ((lane >> 4) & 1) * 8;
                const int kg = ((lane >> 3) & 1) + ks * 2;
                uint32_t bfh[4], bfl[4];
                ldm_x4(bfh, st + TILE_B + tswz(n, kg));
                if (NB == 2) ldm_x4(bfl, st + 2 * TILE_B + tswz(n, kg));
#pragma unroll
                for (int mt = 0; mt < 2; ++mt) {
#pragma unroll
                    for (int s2 = 0; s2 < 2; ++s2) {
                        float* d = acc[mt][p * 2 + s2];
                        mma_fp16(d, afh[mt], bfh + s2 * 2);              // hi*hi
                        if (NB == 2) mma_fp16(d, afh[mt], bfl + s2 * 2); // hi*lo
                    }
                }
            }
        }
    }

    // ---- epilogue ----
    const int r_base = m0 + wm * 32 + (lane >> 2);
    const int c_base = n0 + wn * 64 + (lane & 3) * 2;
#pragma unroll
    for (int mt = 0; mt < 2; ++mt) {
#pragma unroll
        for (int nt = 0; nt < 8; ++nt) {
            const int row = r_base + mt * 16;
            const int col = c_base + nt * 8;
            float v0 = acc[mt][nt][0] * alpha;
            float v1 = acc[mt][nt][1] * alpha;
            float v2 = acc[mt][nt][2] * alpha;
            float v3 = acc[mt][nt][3] * alpha;
            if (bias) {
                const float b0 = bias[z * biasStride + col];
                const float b1 = bias[z * biasStride + col + 1];
                v0 += b0; v1 += b1; v2 += b0; v3 += b1;
            }
            const long long co1 = (long long)row * N + col;
            const long long co2 = co1 + 8ll * N;
            if (wF32) {
                *(float2*)&Cf[z * sCF + co1] = make_float2(v0, v1);
                *(float2*)&Cf[z * sCF + co2] = make_float2(v2, v3);
            } else {
                *(__half2*)&Ch[z * sCH + co1] =
                    __halves2half2(__float2half_rn(v0), __float2half_rn(v1));
                *(__half2*)&Ch[z * sCH + co2] =
                    __halves2half2(__float2half_rn(v2), __float2half_rn(v3));
                if (wLo) {
                    __half h, l0, l1;
                    split2h(v0, h, l0); split2h(v1, h, l1);
                    *(__half2*)&Cl[co1] = __halves2half2(l0, l1);
                    split2h(v2, h, l0); split2h(v3, h, l1);
                    *(__half2*)&Cl[co2] = __halves2half2(l0, l1);
                }
            }
        }
    }
}

// ---------------------------------------------------------------------------
// x -> fp16 hi only (one float4 per thread).
// ---------------------------------------------------------------------------
__global__ __launch_bounds__(256) void splitX(const float* __restrict__ in,
                                              __half* __restrict__ h)
{
    const long long i = (long long)blockIdx.x * 256 + threadIdx.x;
    float4 v = ((const float4*)in)[i];
    ((__half2*)h)[2 * i + 0] = __halves2half2(__float2half_rn(v.x), __float2half_rn(v.y));
    ((__half2*)h)[2 * i + 1] = __halves2half2(__float2half_rn(v.z), __float2half_rn(v.w));
}

// ---------------------------------------------------------------------------
// W -> (hi, lo) fp16 at x32 scale.
// ---------------------------------------------------------------------------
__global__ __launch_bounds__(256) void splitW(const float* __restrict__ in,
                                              __half* __restrict__ h,
                                              __half* __restrict__ l)
{
    const long long i = (long long)blockIdx.x * 256 + threadIdx.x;
    float4 v = ((const float4*)in)[i];
    __half h0, l0, h1, l1, h2, l2, h3, l3;
    split2h(v.x * WSCALE, h0, l0); split2h(v.y * WSCALE, h1, l1);
    split2h(v.z * WSCALE, h2, l2); split2h(v.w * WSCALE, h3, l3);
    ((__half2*)h)[2 * i + 0] = __halves2half2(h0, h1);
    ((__half2*)h)[2 * i + 1] = __halves2half2(h2, h3);
    ((__half2*)l)[2 * i + 0] = __halves2half2(l0, l1);
    ((__half2*)l)[2 * i + 1] = __halves2half2(l2, l3);
}

__global__ void concat_bias(const float* __restrict__ bq, const float* __restrict__ bk,
                            const float* __restrict__ bv, float* __restrict__ dst)
{
    const int i = blockIdx.x * 256 + threadIdx.x;
    if (i < HID)            dst[i] = bq[i];
    else if (i < 2 * HID)   dst[i] = bk[i - HID];
    else if (i < 3 * HID)   dst[i] = bv[i - 2 * HID];
}

// ---------------------------------------------------------------------------
// Batched transpose: V[b][s][h] fp32 -> V^T hi fp16 [b][h][s].
// ---------------------------------------------------------------------------
__global__ __launch_bounds__(256) void transpose_h(const float* __restrict__ V,
                                                   __half* __restrict__ Th)
{
    __shared__ float t[32][33];
    const int b = blockIdx.z;
    const float* Vb = V + (size_t)b * SEQL * HID;
    __half* Thb = Th + (size_t)b * HID * SEQL;
    const int h0 = blockIdx.x * 32;
    const int s0 = blockIdx.y * 32;
    const int tx = threadIdx.x & 31;
    const int ty = threadIdx.x >> 5;
#pragma unroll
    for (int j = 0; j < 4; ++j)
        t[ty + 8 * j][tx] = Vb[(size_t)(s0 + ty + 8 * j) * HID + h0 + tx];
    __syncthreads();
#pragma unroll
    for (int j = 0; j < 4; ++j) {
        const size_t o = (size_t)(h0 + ty + 8 * j) * SEQL + s0 + tx;
        Thb[o] = __float2half_rn(t[tx][ty + 8 * j]);
    }
}

// ---------------------------------------------------------------------------
// Row softmax over fp32 scores -> fp16 hi weights.
// ---------------------------------------------------------------------------
__global__ __launch_bounds__(256) void softmax_h(const float* __restrict__ S,
                                                 __half* __restrict__ Wh)
{
    const float* row = S + (size_t)blockIdx.x * SEQL;
    __half* rh = Wh + (size_t)blockIdx.x * SEQL;
    const int tid = threadIdx.x;
    __shared__ float red[256];

    float vals[16];
    float lmax = -3.402823e38f;
#pragma unroll
    for (int i = 0; i < 4; ++i) {
        float4 t = *(const float4*)&row[(tid + i * 256) * 4];
        vals[i * 4 + 0] = t.x; vals[i * 4 + 1] = t.y;
        vals[i * 4 + 2] = t.z; vals[i * 4 + 3] = t.w;
        lmax = fmaxf(lmax, fmaxf(fmaxf(t.x, t.y), fmaxf(t.z, t.w)));
    }
    red[tid] = lmax;
    __syncthreads();
#pragma unroll
    for (int s = 128; s > 0; s >>= 1) {
        if (tid < s) red[tid] = fmaxf(red[tid], red[tid + s]);
        __syncthreads();
    }
    const float m = red[0];
    __syncthreads();

    float lsum = 0.0f;
#pragma unroll
    for (int i = 0; i < 16; ++i) { vals[i] = expf(vals[i] - m); lsum += vals[i]; }
    red[tid] = lsum;
    __syncthreads();
#pragma unroll
    for (int s = 128; s > 0; s >>= 1) {
        if (tid < s) red[tid] += red[tid + s];
        __syncthreads();
    }
    const float inv = 1.0f / red[0];

#pragma unroll
    for (int i = 0; i < 4; ++i) {
        const int idx = (tid + i * 256) * 4;
        *(__half2*)&rh[idx + 0] = __halves2half2(
            __float2half_rn(vals[i * 4 + 0] * inv), __float2half_rn(vals[i * 4 + 1] * inv));
        *(__half2*)&rh[idx + 2] = __halves2half2(
            __float2half_rn(vals[i * 4 + 2] * inv), __float2half_rn(vals[i * 4 + 3] * inv));
    }
}

// ---------------------------------------------------------------------------
extern "C" void kernel_launch(void* const* d_in, const int* in_sizes, int n_in,
                              void* d_out, int out_size)
{
    (void)in_sizes; (void)n_in; (void)out_size;
    const float* x  = (const float*)d_in[0];
    const float* Wq = (const float*)d_in[1];
    const float* bq = (const float*)d_in[2];
    const float* Wk = (const float*)d_in[3];
    const float* bk = (const float*)d_in[4];
    const float* Wv = (const float*)d_in[5];
    const float* bv = (const float*)d_in[6];
    const float* Wo = (const float*)d_in[7];
    const float* bo = (const float*)d_in[8];
    float* out = (float*)d_out;

    __half *xh, *wh, *wl, *qkh, *kl, *vth, *ph, *oh;
    float *vf, *sf, *bias3;
    cudaGetSymbolAddress((void**)&xh, g_xh);
    cudaGetSymbolAddress((void**)&wh, g_wh);   cudaGetSymbolAddress((void**)&wl, g_wl);
    cudaGetSymbolAddress((void**)&bias3, g_bias3);
    cudaGetSymbolAddress((void**)&qkh, g_qkh); cudaGetSymbolAddress((void**)&kl, g_kl);
    cudaGetSymbolAddress((void**)&vf, g_vf);
    cudaGetSymbolAddress((void**)&vth, g_vth);
    cudaGetSymbolAddress((void**)&sf, g_sf);
    cudaGetSymbolAddress((void**)&ph, g_ph_);
    cudaGetSymbolAddress((void**)&oh, g_oh);

    const int SMEM2 = NSTAGE * 3 * TILE_B;   // 73728 B (2-pass stages)
    const int SMEM1 = NSTAGE * 2 * TILE_B;   // 49152 B (1-pass stages)
    cudaFuncSetAttribute(mmagemm<2>, cudaFuncAttributeMaxDynamicSharedMemorySize, SMEM2);
    cudaFuncSetAttribute(mmagemm<1>, cudaFuncAttributeMaxDynamicSharedMemorySize, SMEM1);

    const size_t WELE = (size_t)HID * HID;
    const long long sQKV = (long long)SEQL * HID;
    const long long sS   = (long long)SEQL * SEQL;
    const long long sPL  = (long long)MTOT * HID;   // plane stride
    const float scl = 0.04419417382415922f;         // 1/sqrt(512)

    // ---- input conversions ----
    splitX<<<(MTOT * (size_t)HID) / 4 / 256, 256>>>(x, xh);
    splitW<<<WELE / 4 / 256, 256>>>(Wq, wh + 0 * WELE, wl + 0 * WELE);
    splitW<<<WELE / 4 / 256, 256>>>(Wk, wh + 1 * WELE, wl + 1 * WELE);
    splitW<<<WELE / 4 / 256, 256>>>(Wv, wh + 2 * WELE, wl + 2 * WELE);
    splitW<<<WELE / 4 / 256, 256>>>(Wo, wh + 3 * WELE, wl + 3 * WELE);
    concat_bias<<<(3 * HID + 255) / 256, 256>>>(bq, bk, bv, bias3);

    // ---- merged QKV projection: z=0 -> Q hi, z=1 -> K hi+lo, z=2 -> V fp32 ----
    mmagemm<2><<<dim3(HID / BN, MTOT / BM, 3), 256, SMEM2>>>(
        xh, wh, wl, bias3, HID, INV_WSCALE,
        vf, qkh, kl,
        HID, HID, /*sAB*/0, /*sBB*/(long long)WELE,
        /*sCH*/sPL, /*sCF*/0, /*f32mask*/0b100, /*lomask*/0b010);

    // ---- V transpose -> fp16 hi ----
    transpose_h<<<dim3(HID / 32, SEQL / 32, BATCH), 256>>>(vf, vth);

    // ---- scores = Q K^T / sqrt(512) (fp32 out, per-batch z) ----
    mmagemm<2><<<dim3(SEQL / BN, SEQL / BM, BATCH), 256, SMEM2>>>(
        qkh, qkh + sPL, kl, nullptr, 0, scl,
        sf, nullptr, nullptr,
        HID, SEQL, sQKV, sQKV, 0, sS, 0xF, 0);

    // ---- softmax -> fp16 hi weights ----
    softmax_h<<<BATCH * SEQL, 256>>>(sf, ph);

    // ---- O = weights @ V^T_hi (single pass), fp16 hi out ----
    mmagemm<1><<<dim3(HID / BN, SEQL / BM, BATCH), 256, SMEM1>>>(
        ph, vth, nullptr, nullptr, 0, 1.0f,
        nullptr, oh, nullptr,
        SEQL, HID, sS, sQKV, sQKV, 0, 0, 0);

    // ---- out = O @ Wo^T + bo (fp32 out) ----
    mmagemm<2><<<dim3(HID / BN, MTOT / BM, 1), 256, SMEM2>>>(
        oh, wh + 3 * WELE, wl + 3 * WELE, bo, 0, INV_WSCALE,
        out, nullptr, nullptr,
        HID, HID, 0, 0, 0, 0, 1, 0);
}

// round 12
// speedup vs baseline: 7.0263x; 1.2637x over previous
#include <cuda_runtime.h>
#include <cuda_fp16.h>
#include <stdint.h>
#include <math.h>

// ---------------------------------------------------------------------------
// WaveInterference via warp-level fp16 mma.sync split GEMMs.
//   QKV projections:   C = x_hi * (W_hi + W_lo)   (2-pass)
//   scores / PV / out: C = A_hi * B_hi            (1-pass)
// Weights pre-scaled x32 so W_lo stays fp16-normal (alpha undoes it).
// B=4, S=4096, H=1024.
// ---------------------------------------------------------------------------

#define BATCH 4
#define SEQL  4096
#define HID   1024
#define MTOT  (BATCH * SEQL)   // 16384

#define BM 128
#define BN 128
#define BK 32
#define TILE_B   8192              // 128 rows x 64 B (32 fp16)
#define NSTAGE   3

#define WSCALE     32.0f
#define INV_WSCALE 0.03125f

// ---------------------------------------------------------------------------
// Device scratch (no allocs allowed anywhere).
// ---------------------------------------------------------------------------
__device__ __half g_xh[(size_t)MTOT * HID];
__device__ __half g_wh[4][(size_t)HID * HID];     // Wq,Wk,Wv,Wo hi (x32)
__device__ __half g_wl[4][(size_t)HID * HID];     // lo (x32)
__device__ float  g_bias3[3 * HID];               // bq|bk|bv concat
__device__ __half g_qkh[2][(size_t)MTOT * HID];   // Q hi, K hi
__device__ float  g_vf[(size_t)MTOT * HID];       // V fp32 (pre-transpose)
__device__ __half g_vth[(size_t)MTOT * HID];      // V^T hi
__device__ float  g_sf[(size_t)BATCH * SEQL * SEQL];   // scores fp32
__device__ __half g_ph_[(size_t)BATCH * SEQL * SEQL];  // softmax weights hi
__device__ __half g_oh[(size_t)MTOT * HID];       // attention out hi

// ---------------------------------------------------------------------------
// PTX helpers (base-target sm_75/sm_80 features only)
// ---------------------------------------------------------------------------
__device__ __forceinline__ uint32_t smem_u32(const void* p) {
    uint32_t a;
    asm("{ .reg .u64 t; cvta.to.shared.u64 t, %1; cvt.u32.u64 %0, t; }" : "=r"(a) : "l"(p));
    return a;
}
__device__ __forceinline__ void cp16(uint32_t dst, const void* src) {
    asm volatile("cp.async.cg.shared.global [%0], [%1], 16;" :: "r"(dst), "l"(src));
}
#define CP_COMMIT() asm volatile("cp.async.commit_group;" ::: "memory")
#define CP_WAIT0()  asm volatile("cp.async.wait_group 0;" ::: "memory")
#define CP_WAIT1()  asm volatile("cp.async.wait_group 1;" ::: "memory")

__device__ __forceinline__ void ldm_x4(uint32_t* r, uint32_t addr) {
    asm volatile("ldmatrix.sync.aligned.m8n8.x4.shared.b16 {%0,%1,%2,%3}, [%4];"
                 : "=r"(r[0]), "=r"(r[1]), "=r"(r[2]), "=r"(r[3]) : "r"(addr));
}
__device__ __forceinline__ void mma_fp16(float* d, const uint32_t* a, const uint32_t* b) {
    asm volatile(
        "mma.sync.aligned.m16n8k16.row.col.f32.f16.f16.f32 "
        "{%0,%1,%2,%3}, {%4,%5,%6,%7}, {%8,%9}, {%0,%1,%2,%3};"
        : "+f"(d[0]), "+f"(d[1]), "+f"(d[2]), "+f"(d[3])
        : "r"(a[0]), "r"(a[1]), "r"(a[2]), "r"(a[3]), "r"(b[0]), "r"(b[1]));
}
__device__ __forceinline__ void split2h(float v, __half& h, __half& l) {
    h = __float2half_rn(v);
    l = __float2half_rn(v - __half2float(h));
}
// 64B-row tile swizzle (conflict-free for cp.async stores + ldmatrix reads).
__device__ __forceinline__ uint32_t tswz(int row, int kg) {
    return (uint32_t)(row * 64 + ((kg ^ ((row >> 1) & 3)) << 4));
}

// ---------------------------------------------------------------------------
// Split-fp16 NT GEMM, NB = B planes (2: hi+lo, 1: hi only).
//   C = alpha * (A_hi @ (Bh[+Bl])^T) + bias
//   A[M,K] K-major fp16 hi; B[N,K] K-major. 3-stage cp.async pipeline.
//   Per-z output mode: fp32 if (f32mask>>z)&1 else fp16.
// 256 threads, 8 warps (4m x 2n), warp tile 32x64, fp32 register accumulators.
// ---------------------------------------------------------------------------
template <int NB>
__global__ __launch_bounds__(256, 2) void mmagemm(
    const __half* __restrict__ Ah,
    const __half* __restrict__ Bh, const __half* __restrict__ Bl,
    const float* __restrict__ bias, int biasStride, float alpha,
    float* __restrict__ Cf, __half* __restrict__ Ch,
    int K, int N, long long sAB, long long sBB,
    long long sCH, long long sCF, int f32mask)
{
    constexpr int NT      = 1 + NB;            // tiles per stage
    constexpr int STAGE_B = NT * TILE_B;

    extern __shared__ char smem[];
    const uint32_t sb = smem_u32(smem);
    const int tid  = threadIdx.x;
    const int lane = tid & 31;
    const int wid  = tid >> 5;
    const int wm   = wid & 3;
    const int wn   = wid >> 2;
    const int z    = blockIdx.z;
    const int m0   = blockIdx.y * BM;
    const int n0   = blockIdx.x * BN;
    const bool wF32 = (f32mask >> z) & 1;

    const __half* srcs[NT];
    srcs[0] = Ah + (long long)z * sAB + (long long)m0 * K;
    srcs[1] = Bh + (long long)z * sBB + (long long)n0 * K;
    if (NB == 2) srcs[2] = Bl + (long long)z * sBB + (long long)n0 * K;

    float acc[2][8][4];
#pragma unroll
    for (int i = 0; i < 2; i++)
#pragma unroll
        for (int j = 0; j < 8; j++)
#pragma unroll
            for (int q = 0; q < 4; q++) acc[i][j][q] = 0.0f;

    const int KC = K / BK;

    auto load_stage = [&](int s, int k0) {
        const uint32_t base = sb + s * STAGE_B;
#pragma unroll
        for (int t = 0; t < NT; t++) {
#pragma unroll
            for (int h = 0; h < 2; h++) {
                const int c = tid + h * 256;     // 0..511
                const int row = c >> 2;
                const int kg  = c & 3;
                cp16(base + t * TILE_B + tswz(row, kg),
                     srcs[t] + (long long)row * K + k0 + kg * 8);
            }
        }
        CP_COMMIT();
    };

    load_stage(0, 0);
    load_stage(1, BK);

    for (int c = 0; c < KC; ++c) {
        if (c == KC - 1) CP_WAIT0(); else CP_WAIT1();
        __syncthreads();                 // stage c ready; compute c-1 done
        if (c + 2 < KC) {
            const int s2i = c + 2;
            load_stage(s2i % NSTAGE, s2i * BK);
        }

        const uint32_t st = sb + (c % NSTAGE) * STAGE_B;
#pragma unroll
        for (int ks = 0; ks < 2; ++ks) {
            uint32_t afh[2][4];
#pragma unroll
            for (int mt = 0; mt < 2; ++mt) {
                const int row = wm * 32 + mt * 16 + (lane & 15);
                const int kg  = (lane >> 4) + ks * 2;
                ldm_x4(afh[mt], st + tswz(row, kg));
            }
#pragma unroll
            for (int p = 0; p < 4; ++p) {
                const int n  = wn * 64 + p * 16 + (lane & 7) + ((lane >> 4) & 1) * 8;
                const int kg = ((lane >> 3) & 1) + ks * 2;
                uint32_t bfh[4], bfl[4];
                ldm_x4(bfh, st + TILE_B + tswz(n, kg));
                if (NB == 2) ldm_x4(bfl, st + 2 * TILE_B + tswz(n, kg));
#pragma unroll
                for (int mt = 0; mt < 2; ++mt) {
#pragma unroll
                    for (int s2 = 0; s2 < 2; ++s2) {
                        float* d = acc[mt][p * 2 + s2];
                        mma_fp16(d, afh[mt], bfh + s2 * 2);              // hi*hi
                        if (NB == 2) mma_fp16(d, afh[mt], bfl + s2 * 2); // hi*lo
                    }
                }
            }
        }
    }

    // ---- epilogue ----
    const int r_base = m0 + wm * 32 + (lane >> 2);
    const int c_base = n0 + wn * 64 + (lane & 3) * 2;
#pragma unroll
    for (int mt = 0; mt < 2; ++mt) {
#pragma unroll
        for (int nt = 0; nt < 8; ++nt) {
            const int row = r_base + mt * 16;
            const int col = c_base + nt * 8;
            float v0 = acc[mt][nt][0] * alpha;
            float v1 = acc[mt][nt][1] * alpha;
            float v2 = acc[mt][nt][2] * alpha;
            float v3 = acc[mt][nt][3] * alpha;
            if (bias) {
                const float b0 = bias[z * biasStride + col];
                const float b1 = bias[z * biasStride + col + 1];
                v0 += b0; v1 += b1; v2 += b0; v3 += b1;
            }
            const long long co1 = (long long)row * N + col;
            const long long co2 = co1 + 8ll * N;
            if (wF32) {
                *(float2*)&Cf[z * sCF + co1] = make_float2(v0, v1);
                *(float2*)&Cf[z * sCF + co2] = make_float2(v2, v3);
            } else {
                *(__half2*)&Ch[z * sCH + co1] =
                    __halves2half2(__float2half_rn(v0), __float2half_rn(v1));
                *(__half2*)&Ch[z * sCH + co2] =
                    __halves2half2(__float2half_rn(v2), __float2half_rn(v3));
            }
        }
    }
}

// ---------------------------------------------------------------------------
// x -> fp16 hi only (one float4 per thread).
// ---------------------------------------------------------------------------
__global__ __launch_bounds__(256) void splitX(const float* __restrict__ in,
                                              __half* __restrict__ h)
{
    const long long i = (long long)blockIdx.x * 256 + threadIdx.x;
    float4 v = ((const float4*)in)[i];
    ((__half2*)h)[2 * i + 0] = __halves2half2(__float2half_rn(v.x), __float2half_rn(v.y));
    ((__half2*)h)[2 * i + 1] = __halves2half2(__float2half_rn(v.z), __float2half_rn(v.w));
}

// ---------------------------------------------------------------------------
// W -> (hi, lo) fp16 at x32 scale.
// ---------------------------------------------------------------------------
__global__ __launch_bounds__(256) void splitW(const float* __restrict__ in,
                                              __half* __restrict__ h,
                                              __half* __restrict__ l)
{
    const long long i = (long long)blockIdx.x * 256 + threadIdx.x;
    float4 v = ((const float4*)in)[i];
    __half h0, l0, h1, l1, h2, l2, h3, l3;
    split2h(v.x * WSCALE, h0, l0); split2h(v.y * WSCALE, h1, l1);
    split2h(v.z * WSCALE, h2, l2); split2h(v.w * WSCALE, h3, l3);
    ((__half2*)h)[2 * i + 0] = __halves2half2(h0, h1);
    ((__half2*)h)[2 * i + 1] = __halves2half2(h2, h3);
    ((__half2*)l)[2 * i + 0] = __halves2half2(l0, l1);
    ((__half2*)l)[2 * i + 1] = __halves2half2(l2, l3);
}

// W -> fp16 hi only at x32 scale (Wo: used single-pass).
__global__ __launch_bounds__(256) void splitWh(const float* __restrict__ in,
                                               __half* __restrict__ h)
{
    const long long i = (long long)blockIdx.x * 256 + threadIdx.x;
    float4 v = ((const float4*)in)[i];
    ((__half2*)h)[2 * i + 0] = __halves2half2(__float2half_rn(v.x * WSCALE),
                                              __float2half_rn(v.y * WSCALE));
    ((__half2*)h)[2 * i + 1] = __halves2half2(__float2half_rn(v.z * WSCALE),
                                              __float2half_rn(v.w * WSCALE));
}

__global__ void concat_bias(const float* __restrict__ bq, const float* __restrict__ bk,
                            const float* __restrict__ bv, float* __restrict__ dst)
{
    const int i = blockIdx.x * 256 + threadIdx.x;
    if (i < HID)            dst[i] = bq[i];
    else if (i < 2 * HID)   dst[i] = bk[i - HID];
    else if (i < 3 * HID)   dst[i] = bv[i - 2 * HID];
}

// ---------------------------------------------------------------------------
// Batched transpose: V[b][s][h] fp32 -> V^T hi fp16 [b][h][s].
// ---------------------------------------------------------------------------
__global__ __launch_bounds__(256) void transpose_h(const float* __restrict__ V,
                                                   __half* __restrict__ Th)
{
    __shared__ float t[32][33];
    const int b = blockIdx.z;
    const float* Vb = V + (size_t)b * SEQL * HID;
    __half* Thb = Th + (size_t)b * HID * SEQL;
    const int h0 = blockIdx.x * 32;
    const int s0 = blockIdx.y * 32;
    const int tx = threadIdx.x & 31;
    const int ty = threadIdx.x >> 5;
#pragma unroll
    for (int j = 0; j < 4; ++j)
        t[ty + 8 * j][tx] = Vb[(size_t)(s0 + ty + 8 * j) * HID + h0 + tx];
    __syncthreads();
#pragma unroll
    for (int j = 0; j < 4; ++j) {
        const size_t o = (size_t)(h0 + ty + 8 * j) * SEQL + s0 + tx;
        Thb[o] = __float2half_rn(t[tx][ty + 8 * j]);
    }
}

// ---------------------------------------------------------------------------
// Row softmax over fp32 scores -> fp16 hi weights.
// ---------------------------------------------------------------------------
__global__ __launch_bounds__(256) void softmax_h(const float* __restrict__ S,
                                                 __half* __restrict__ Wh)
{
    const float* row = S + (size_t)blockIdx.x * SEQL;
    __half* rh = Wh + (size_t)blockIdx.x * SEQL;
    const int tid = threadIdx.x;
    __shared__ float red[256];

    float vals[16];
    float lmax = -3.402823e38f;
#pragma unroll
    for (int i = 0; i < 4; ++i) {
        float4 t = *(const float4*)&row[(tid + i * 256) * 4];
        vals[i * 4 + 0] = t.x; vals[i * 4 + 1] = t.y;
        vals[i * 4 + 2] = t.z; vals[i * 4 + 3] = t.w;
        lmax = fmaxf(lmax, fmaxf(fmaxf(t.x, t.y), fmaxf(t.z, t.w)));
    }
    red[tid] = lmax;
    __syncthreads();
#pragma unroll
    for (int s = 128; s > 0; s >>= 1) {
        if (tid < s) red[tid] = fmaxf(red[tid], red[tid + s]);
        __syncthreads();
    }
    const float m = red[0];
    __syncthreads();

    float lsum = 0.0f;
#pragma unroll
    for (int i = 0; i < 16; ++i) { vals[i] = expf(vals[i] - m); lsum += vals[i]; }
    red[tid] = lsum;
    __syncthreads();
#pragma unroll
    for (int s = 128; s > 0; s >>= 1) {
        if (tid < s) red[tid] += red[tid + s];
        __syncthreads();
    }
    const float inv = 1.0f / red[0];

#pragma unroll
    for (int i = 0; i < 4; ++i) {
        const int idx = (tid + i * 256) * 4;
        *(__half2*)&rh[idx + 0] = __halves2half2(
            __float2half_rn(vals[i * 4 + 0] * inv), __float2half_rn(vals[i * 4 + 1] * inv));
        *(__half2*)&rh[idx + 2] = __halves2half2(
            __float2half_rn(vals[i * 4 + 2] * inv), __float2half_rn(vals[i * 4 + 3] * inv));
    }
}

// ---------------------------------------------------------------------------
extern "C" void kernel_launch(void* const* d_in, const int* in_sizes, int n_in,
                              void* d_out, int out_size)
{
    (void)in_sizes; (void)n_in; (void)out_size;
    const float* x  = (const float*)d_in[0];
    const float* Wq = (const float*)d_in[1];
    const float* bq = (const float*)d_in[2];
    const float* Wk = (const float*)d_in[3];
    const float* bk = (const float*)d_in[4];
    const float* Wv = (const float*)d_in[5];
    const float* bv = (const float*)d_in[6];
    const float* Wo = (const float*)d_in[7];
    const float* bo = (const float*)d_in[8];
    float* out = (float*)d_out;

    __half *xh, *wh, *wl, *qkh, *vth, *ph, *oh;
    float *vf, *sf, *bias3;
    cudaGetSymbolAddress((void**)&xh, g_xh);
    cudaGetSymbolAddress((void**)&wh, g_wh);   cudaGetSymbolAddress((void**)&wl, g_wl);
    cudaGetSymbolAddress((void**)&bias3, g_bias3);
    cudaGetSymbolAddress((void**)&qkh, g_qkh);
    cudaGetSymbolAddress((void**)&vf, g_vf);
    cudaGetSymbolAddress((void**)&vth, g_vth);
    cudaGetSymbolAddress((void**)&sf, g_sf);
    cudaGetSymbolAddress((void**)&ph, g_ph_);
    cudaGetSymbolAddress((void**)&oh, g_oh);

    const int SMEM2 = NSTAGE * 3 * TILE_B;   // 73728 B (2-pass stages)
    const int SMEM1 = NSTAGE * 2 * TILE_B;   // 49152 B (1-pass stages)
    cudaFuncSetAttribute(mmagemm<2>, cudaFuncAttributeMaxDynamicSharedMemorySize, SMEM2);
    cudaFuncSetAttribute(mmagemm<1>, cudaFuncAttributeMaxDynamicSharedMemorySize, SMEM1);

    const size_t WELE = (size_t)HID * HID;
    const long long sQKV = (long long)SEQL * HID;
    const long long sS   = (long long)SEQL * SEQL;
    const long long sPL  = (long long)MTOT * HID;   // plane stride
    const float scl = 0.04419417382415922f;         // 1/sqrt(512)

    // ---- input conversions ----
    splitX<<<(MTOT * (size_t)HID) / 4 / 256, 256>>>(x, xh);
    splitW<<<WELE / 4 / 256, 256>>>(Wq, wh + 0 * WELE, wl + 0 * WELE);
    splitW<<<WELE / 4 / 256, 256>>>(Wk, wh + 1 * WELE, wl + 1 * WELE);
    splitW<<<WELE / 4 / 256, 256>>>(Wv, wh + 2 * WELE, wl + 2 * WELE);
    splitWh<<<WELE / 4 / 256, 256>>>(Wo, wh + 3 * WELE);
    concat_bias<<<(3 * HID + 255) / 256, 256>>>(bq, bk, bv, bias3);

    // ---- merged QKV projection: z=0 -> Q hi, z=1 -> K hi, z=2 -> V fp32 ----
    mmagemm<2><<<dim3(HID / BN, MTOT / BM, 3), 256, SMEM2>>>(
        xh, wh, wl, bias3, HID, INV_WSCALE,
        vf, qkh,
        HID, HID, /*sAB*/0, /*sBB*/(long long)WELE,
        /*sCH*/sPL, /*sCF*/0, /*f32mask*/0b100);

    // ---- V transpose -> fp16 hi ----
    transpose_h<<<dim3(HID / 32, SEQL / 32, BATCH), 256>>>(vf, vth);

    // ---- scores = Q K^T / sqrt(512) (single pass, fp32 out, per-batch z) ----
    mmagemm<1><<<dim3(SEQL / BN, SEQL / BM, BATCH), 256, SMEM1>>>(
        qkh, qkh + sPL, nullptr, nullptr, 0, scl,
        sf, nullptr,
        HID, SEQL, sQKV, sQKV, 0, sS, 0xF);

    // ---- softmax -> fp16 hi weights ----
    softmax_h<<<BATCH * SEQL, 256>>>(sf, ph);

    // ---- O = weights @ V^T_hi (single pass), fp16 hi out ----
    mmagemm<1><<<dim3(HID / BN, SEQL / BM, BATCH), 256, SMEM1>>>(
        ph, vth, nullptr, nullptr, 0, 1.0f,
        nullptr, oh,
        SEQL, HID, sS, sQKV, sQKV, 0, 0);

    // ---- out = O @ Wo^T_hi + bo (single pass, fp32 out) ----
    mmagemm<1><<<dim3(HID / BN, MTOT / BM, 1), 256, SMEM1>>>(
        oh, wh + 3 * WELE, nullptr, bo, 0, INV_WSCALE,
        out, nullptr,
        HID, HID, 0, 0, 0, 0, 1);
}

// round 13
// speedup vs baseline: 8.2962x; 1.1807x over previous
#include <cuda_runtime.h>
#include <cuda_fp16.h>
#include <stdint.h>
#include <math.h>

// ---------------------------------------------------------------------------
// WaveInterference via warp-level fp16 mma.sync, all GEMMs single-pass fp16:
//   C = A_hi @ B_hi^T (+bias), fp32 accumulate.
// All operand planes rounded once to fp16 (10 rounding planes total,
// modeled rel_err ~7.2e-4 < 1e-3). Weights pre-scaled x32 (alpha undoes it).
// B=4, S=4096, H=1024.
// ---------------------------------------------------------------------------

#define BATCH 4
#define SEQL  4096
#define HID   1024
#define MTOT  (BATCH * SEQL)   // 16384

#define BM 128
#define BN 128
#define BK 32
#define TILE_B   8192              // 128 rows x 64 B (32 fp16)
#define NSTAGE   3
#define STAGE_B  (2 * TILE_B)      // A, B tiles
#define SMEM_SZ  (NSTAGE * STAGE_B) // 49152 B

#define WSCALE     32.0f
#define INV_WSCALE 0.03125f

// ---------------------------------------------------------------------------
// Device scratch (no allocs allowed anywhere).
// ---------------------------------------------------------------------------
__device__ __half g_xh[(size_t)MTOT * HID];
__device__ __half g_wh[4][(size_t)HID * HID];     // Wq,Wk,Wv,Wo hi (x32)
__device__ float  g_bias3[3 * HID];               // bq|bk|bv concat
__device__ __half g_qkh[2][(size_t)MTOT * HID];   // Q hi, K hi
__device__ float  g_vf[(size_t)MTOT * HID];       // V fp32 (pre-transpose)
__device__ __half g_vth[(size_t)MTOT * HID];      // V^T hi
__device__ float  g_sf[(size_t)BATCH * SEQL * SEQL];   // scores fp32
__device__ __half g_ph_[(size_t)BATCH * SEQL * SEQL];  // softmax weights hi
__device__ __half g_oh[(size_t)MTOT * HID];       // attention out hi

// ---------------------------------------------------------------------------
// PTX helpers (base-target sm_75/sm_80 features only)
// ---------------------------------------------------------------------------
__device__ __forceinline__ uint32_t smem_u32(const void* p) {
    uint32_t a;
    asm("{ .reg .u64 t; cvta.to.shared.u64 t, %1; cvt.u32.u64 %0, t; }" : "=r"(a) : "l"(p));
    return a;
}
__device__ __forceinline__ void cp16(uint32_t dst, const void* src) {
    asm volatile("cp.async.cg.shared.global [%0], [%1], 16;" :: "r"(dst), "l"(src));
}
#define CP_COMMIT() asm volatile("cp.async.commit_group;" ::: "memory")
#define CP_WAIT0()  asm volatile("cp.async.wait_group 0;" ::: "memory")
#define CP_WAIT1()  asm volatile("cp.async.wait_group 1;" ::: "memory")

__device__ __forceinline__ void ldm_x4(uint32_t* r, uint32_t addr) {
    asm volatile("ldmatrix.sync.aligned.m8n8.x4.shared.b16 {%0,%1,%2,%3}, [%4];"
                 : "=r"(r[0]), "=r"(r[1]), "=r"(r[2]), "=r"(r[3]) : "r"(addr));
}
__device__ __forceinline__ void mma_fp16(float* d, const uint32_t* a, const uint32_t* b) {
    asm volatile(
        "mma.sync.aligned.m16n8k16.row.col.f32.f16.f16.f32 "
        "{%0,%1,%2,%3}, {%4,%5,%6,%7}, {%8,%9}, {%0,%1,%2,%3};"
        : "+f"(d[0]), "+f"(d[1]), "+f"(d[2]), "+f"(d[3])
        : "r"(a[0]), "r"(a[1]), "r"(a[2]), "r"(a[3]), "r"(b[0]), "r"(b[1]));
}
// 64B-row tile swizzle (conflict-free for cp.async stores + ldmatrix reads).
__device__ __forceinline__ uint32_t tswz(int row, int kg) {
    return (uint32_t)(row * 64 + ((kg ^ ((row >> 1) & 3)) << 4));
}

// ---------------------------------------------------------------------------
// Single-pass fp16 NT GEMM: C = alpha * (A_hi @ B_hi^T) + bias
//   A[M,K], B[N,K] K-major fp16. 3-stage cp.async pipeline.
//   Per-z output mode: fp32 if (f32mask>>z)&1 else fp16.
// 256 threads, 8 warps (4m x 2n), warp tile 32x64, fp32 register accumulators.
// ---------------------------------------------------------------------------
__global__ __launch_bounds__(256, 2) void mmagemm(
    const __half* __restrict__ Ah, const __half* __restrict__ Bh,
    const float* __restrict__ bias, int biasStride, float alpha,
    float* __restrict__ Cf, __half* __restrict__ Ch,
    int K, int N, long long sAB, long long sBB,
    long long sCH, long long sCF, int f32mask)
{
    extern __shared__ char smem[];
    const uint32_t sb = smem_u32(smem);
    const int tid  = threadIdx.x;
    const int lane = tid & 31;
    const int wid  = tid >> 5;
    const int wm   = wid & 3;
    const int wn   = wid >> 2;
    const int z    = blockIdx.z;
    const int m0   = blockIdx.y * BM;
    const int n0   = blockIdx.x * BN;
    const bool wF32 = (f32mask >> z) & 1;

    const __half* srcA = Ah + (long long)z * sAB + (long long)m0 * K;
    const __half* srcB = Bh + (long long)z * sBB + (long long)n0 * K;

    float acc[2][8][4];
#pragma unroll
    for (int i = 0; i < 2; i++)
#pragma unroll
        for (int j = 0; j < 8; j++)
#pragma unroll
            for (int q = 0; q < 4; q++) acc[i][j][q] = 0.0f;

    const int KC = K / BK;

    auto load_stage = [&](int s, int k0) {
        const uint32_t base = sb + s * STAGE_B;
#pragma unroll
        for (int h = 0; h < 2; h++) {
            const int c = tid + h * 256;     // 0..511
            const int row = c >> 2;
            const int kg  = c & 3;
            const uint32_t so = tswz(row, kg);
            const long long go = (long long)row * K + k0 + kg * 8;
            cp16(base + so, srcA + go);
            cp16(base + TILE_B + so, srcB + go);
        }
        CP_COMMIT();
    };

    load_stage(0, 0);
    load_stage(1, BK);

    for (int c = 0; c < KC; ++c) {
        if (c == KC - 1) CP_WAIT0(); else CP_WAIT1();
        __syncthreads();                 // stage c ready; compute c-1 done
        if (c + 2 < KC) {
            const int s2i = c + 2;
            load_stage(s2i % NSTAGE, s2i * BK);
        }

        const uint32_t st = sb + (c % NSTAGE) * STAGE_B;
#pragma unroll
        for (int ks = 0; ks < 2; ++ks) {
            uint32_t afh[2][4];
#pragma unroll
            for (int mt = 0; mt < 2; ++mt) {
                const int row = wm * 32 + mt * 16 + (lane & 15);
                const int kg  = (lane >> 4) + ks * 2;
                ldm_x4(afh[mt], st + tswz(row, kg));
            }
#pragma unroll
            for (int p = 0; p < 4; ++p) {
                const int n  = wn * 64 + p * 16 + (lane & 7) + ((lane >> 4) & 1) * 8;
                const int kg = ((lane >> 3) & 1) + ks * 2;
                uint32_t bfh[4];
                ldm_x4(bfh, st + TILE_B + tswz(n, kg));
#pragma unroll
                for (int mt = 0; mt < 2; ++mt) {
#pragma unroll
                    for (int s2 = 0; s2 < 2; ++s2)
                        mma_fp16(acc[mt][p * 2 + s2], afh[mt], bfh + s2 * 2);
                }
            }
        }
    }

    // ---- epilogue ----
    const int r_base = m0 + wm * 32 + (lane >> 2);
    const int c_base = n0 + wn * 64 + (lane & 3) * 2;
#pragma unroll
    for (int mt = 0; mt < 2; ++mt) {
#pragma unroll
        for (int nt = 0; nt < 8; ++nt) {
            const int row = r_base + mt * 16;
            const int col = c_base + nt * 8;
            float v0 = acc[mt][nt][0] * alpha;
            float v1 = acc[mt][nt][1] * alpha;
            float v2 = acc[mt][nt][2] * alpha;
            float v3 = acc[mt][nt][3] * alpha;
            if (bias) {
                const float b0 = bias[z * biasStride + col];
                const float b1 = bias[z * biasStride + col + 1];
                v0 += b0; v1 += b1; v2 += b0; v3 += b1;
            }
            const long long co1 = (long long)row * N + col;
            const long long co2 = co1 + 8ll * N;
            if (wF32) {
                *(float2*)&Cf[z * sCF + co1] = make_float2(v0, v1);
                *(float2*)&Cf[z * sCF + co2] = make_float2(v2, v3);
            } else {
                *(__half2*)&Ch[z * sCH + co1] =
                    __halves2half2(__float2half_rn(v0), __float2half_rn(v1));
                *(__half2*)&Ch[z * sCH + co2] =
                    __halves2half2(__float2half_rn(v2), __float2half_rn(v3));
            }
        }
    }
}

// ---------------------------------------------------------------------------
// fp32 -> fp16 with scale (one float4 per thread).
// ---------------------------------------------------------------------------
__global__ __launch_bounds__(256) void cvt_h(const float* __restrict__ in,
                                             __half* __restrict__ h, float scale)
{
    const long long i = (long long)blockIdx.x * 256 + threadIdx.x;
    float4 v = ((const float4*)in)[i];
    ((__half2*)h)[2 * i + 0] = __halves2half2(__float2half_rn(v.x * scale),
                                              __float2half_rn(v.y * scale));
    ((__half2*)h)[2 * i + 1] = __halves2half2(__float2half_rn(v.z * scale),
                                              __float2half_rn(v.w * scale));
}

__global__ void concat_bias(const float* __restrict__ bq, const float* __restrict__ bk,
                            const float* __restrict__ bv, float* __restrict__ dst)
{
    const int i = blockIdx.x * 256 + threadIdx.x;
    if (i < HID)            dst[i] = bq[i];
    else if (i < 2 * HID)   dst[i] = bk[i - HID];
    else if (i < 3 * HID)   dst[i] = bv[i - 2 * HID];
}

// ---------------------------------------------------------------------------
// Batched transpose: V[b][s][h] fp32 -> V^T hi fp16 [b][h][s].
// ---------------------------------------------------------------------------
__global__ __launch_bounds__(256) void transpose_h(const float* __restrict__ V,
                                                   __half* __restrict__ Th)
{
    __shared__ float t[32][33];
    const int b = blockIdx.z;
    const float* Vb = V + (size_t)b * SEQL * HID;
    __half* Thb = Th + (size_t)b * HID * SEQL;
    const int h0 = blockIdx.x * 32;
    const int s0 = blockIdx.y * 32;
    const int tx = threadIdx.x & 31;
    const int ty = threadIdx.x >> 5;
#pragma unroll
    for (int j = 0; j < 4; ++j)
        t[ty + 8 * j][tx] = Vb[(size_t)(s0 + ty + 8 * j) * HID + h0 + tx];
    __syncthreads();
#pragma unroll
    for (int j = 0; j < 4; ++j) {
        const size_t o = (size_t)(h0 + ty + 8 * j) * SEQL + s0 + tx;
        Thb[o] = __float2half_rn(t[tx][ty + 8 * j]);
    }
}

// ---------------------------------------------------------------------------
// Row softmax over fp32 scores -> fp16 hi weights.
// ---------------------------------------------------------------------------
__global__ __launch_bounds__(256) void softmax_h(const float* __restrict__ S,
                                                 __half* __restrict__ Wh)
{
    const float* row = S + (size_t)blockIdx.x * SEQL;
    __half* rh = Wh + (size_t)blockIdx.x * SEQL;
    const int tid = threadIdx.x;
    __shared__ float red[256];

    float vals[16];
    float lmax = -3.402823e38f;
#pragma unroll
    for (int i = 0; i < 4; ++i) {
        float4 t = *(const float4*)&row[(tid + i * 256) * 4];
        vals[i * 4 + 0] = t.x; vals[i * 4 + 1] = t.y;
        vals[i * 4 + 2] = t.z; vals[i * 4 + 3] = t.w;
        lmax = fmaxf(lmax, fmaxf(fmaxf(t.x, t.y), fmaxf(t.z, t.w)));
    }
    red[tid] = lmax;
    __syncthreads();
#pragma unroll
    for (int s = 128; s > 0; s >>= 1) {
        if (tid < s) red[tid] = fmaxf(red[tid], red[tid + s]);
        __syncthreads();
    }
    const float m = red[0];
    __syncthreads();

    float lsum = 0.0f;
#pragma unroll
    for (int i = 0; i < 16; ++i) { vals[i] = expf(vals[i] - m); lsum += vals[i]; }
    red[tid] = lsum;
    __syncthreads();
#pragma unroll
    for (int s = 128; s > 0; s >>= 1) {
        if (tid < s) red[tid] += red[tid + s];
        __syncthreads();
    }
    const float inv = 1.0f / red[0];

#pragma unroll
    for (int i = 0; i < 4; ++i) {
        const int idx = (tid + i * 256) * 4;
        *(__half2*)&rh[idx + 0] = __halves2half2(
            __float2half_rn(vals[i * 4 + 0] * inv), __float2half_rn(vals[i * 4 + 1] * inv));
        *(__half2*)&rh[idx + 2] = __halves2half2(
            __float2half_rn(vals[i * 4 + 2] * inv), __float2half_rn(vals[i * 4 + 3] * inv));
    }
}

// ---------------------------------------------------------------------------
extern "C" void kernel_launch(void* const* d_in, const int* in_sizes, int n_in,
                              void* d_out, int out_size)
{
    (void)in_sizes; (void)n_in; (void)out_size;
    const float* x  = (const float*)d_in[0];
    const float* Wq = (const float*)d_in[1];
    const float* bq = (const float*)d_in[2];
    const float* Wk = (const float*)d_in[3];
    const float* bk = (const float*)d_in[4];
    const float* Wv = (const float*)d_in[5];
    const float* bv = (const float*)d_in[6];
    const float* Wo = (const float*)d_in[7];
    const float* bo = (const float*)d_in[8];
    float* out = (float*)d_out;

    __half *xh, *wh, *qkh, *vth, *ph, *oh;
    float *vf, *sf, *bias3;
    cudaGetSymbolAddress((void**)&xh, g_xh);
    cudaGetSymbolAddress((void**)&wh, g_wh);
    cudaGetSymbolAddress((void**)&bias3, g_bias3);
    cudaGetSymbolAddress((void**)&qkh, g_qkh);
    cudaGetSymbolAddress((void**)&vf, g_vf);
    cudaGetSymbolAddress((void**)&vth, g_vth);
    cudaGetSymbolAddress((void**)&sf, g_sf);
    cudaGetSymbolAddress((void**)&ph, g_ph_);
    cudaGetSymbolAddress((void**)&oh, g_oh);

    cudaFuncSetAttribute(mmagemm, cudaFuncAttributeMaxDynamicSharedMemorySize, SMEM_SZ);

    const size_t WELE = (size_t)HID * HID;
    const long long sQKV = (long long)SEQL * HID;
    const long long sS   = (long long)SEQL * SEQL;
    const long long sPL  = (long long)MTOT * HID;   // plane stride
    const float scl = 0.04419417382415922f;         // 1/sqrt(512)

    // ---- input conversions (all single-plane fp16; weights x32) ----
    cvt_h<<<(MTOT * (size_t)HID) / 4 / 256, 256>>>(x, xh, 1.0f);
    cvt_h<<<WELE / 4 / 256, 256>>>(Wq, wh + 0 * WELE, WSCALE);
    cvt_h<<<WELE / 4 / 256, 256>>>(Wk, wh + 1 * WELE, WSCALE);
    cvt_h<<<WELE / 4 / 256, 256>>>(Wv, wh + 2 * WELE, WSCALE);
    cvt_h<<<WELE / 4 / 256, 256>>>(Wo, wh + 3 * WELE, WSCALE);
    concat_bias<<<(3 * HID + 255) / 256, 256>>>(bq, bk, bv, bias3);

    // ---- merged QKV projection: z=0 -> Q hi, z=1 -> K hi, z=2 -> V fp32 ----
    mmagemm<<<dim3(HID / BN, MTOT / BM, 3), 256, SMEM_SZ>>>(
        xh, wh, bias3, HID, INV_WSCALE,
        vf, qkh,
        HID, HID, /*sAB*/0, /*sBB*/(long long)WELE,
        /*sCH*/sPL, /*sCF*/0, /*f32mask*/0b100);

    // ---- V transpose -> fp16 hi ----
    transpose_h<<<dim3(HID / 32, SEQL / 32, BATCH), 256>>>(vf, vth);

    // ---- scores = Q K^T / sqrt(512) (fp32 out, per-batch z) ----
    mmagemm<<<dim3(SEQL / BN, SEQL / BM, BATCH), 256, SMEM_SZ>>>(
        qkh, qkh + sPL, nullptr, 0, scl,
        sf, nullptr,
        HID, SEQL, sQKV, sQKV, 0, sS, 0xF);

    // ---- softmax -> fp16 hi weights ----
    softmax_h<<<BATCH * SEQL, 256>>>(sf, ph);

    // ---- O = weights @ V^T_hi, fp16 hi out ----
    mmagemm<<<dim3(HID / BN, SEQL / BM, BATCH), 256, SMEM_SZ>>>(
        ph, vth, nullptr, 0, 1.0f,
        nullptr, oh,
        SEQL, HID, sS, sQKV, sQKV, 0, 0);

    // ---- out = O @ Wo^T_hi + bo (fp32 out) ----
    mmagemm<<<dim3(HID / BN, MTOT / BM, 1), 256, SMEM_SZ>>>(
        oh, wh + 3 * WELE, bo, 0, INV_WSCALE,
        out, nullptr,
        HID, HID, 0, 0, 0, 0, 1);
}

// round 14
// speedup vs baseline: 9.2449x; 1.1143x over previous
#include <cuda_runtime.h>
#include <cuda_fp16.h>
#include <stdint.h>
#include <math.h>

// ---------------------------------------------------------------------------
// WaveInterference via warp-level fp16 mma.sync, all GEMMs single-pass fp16:
//   C = A_hi @ B_hi^T (+bias), fp32 accumulate. BK=64, 3-stage cp.async.
// QKV projection writes V^T fp16 directly via smem transpose (z=2).
// Weights pre-scaled x32 (alpha undoes it). B=4, S=4096, H=1024.
// ---------------------------------------------------------------------------

#define BATCH 4
#define SEQL  4096
#define HID   1024
#define MTOT  (BATCH * SEQL)   // 16384

#define BM 128
#define BN 128
#define BK 64
#define TILE_B   16384             // 128 rows x 128 B (64 fp16)
#define NSTAGE   3
#define STAGE_B  (2 * TILE_B)      // A, B tiles = 32 KB
#define SMEM_SZ  (NSTAGE * STAGE_B) // 98304 B; x2 CTAs = 192 KB <= 228 KB

#define TP 136                     // transpose smem pitch (halves)

#define WSCALE     32.0f
#define INV_WSCALE 0.03125f

// ---------------------------------------------------------------------------
// Device scratch (no allocs allowed anywhere).
// ---------------------------------------------------------------------------
__device__ __half g_xh[(size_t)MTOT * HID];
__device__ __half g_wh[4][(size_t)HID * HID];     // Wq,Wk,Wv,Wo hi (x32)
__device__ float  g_bias3[3 * HID];               // bq|bk|bv concat
__device__ __half g_qkh[2][(size_t)MTOT * HID];   // Q hi, K hi
__device__ __half g_vth[(size_t)MTOT * HID];      // V^T hi [b][h][s]
__device__ float  g_sf[(size_t)BATCH * SEQL * SEQL];   // scores fp32
__device__ __half g_ph_[(size_t)BATCH * SEQL * SEQL];  // softmax weights hi
__device__ __half g_oh[(size_t)MTOT * HID];       // attention out hi

// ---------------------------------------------------------------------------
// PTX helpers (base-target sm_75/sm_80 features only)
// ---------------------------------------------------------------------------
__device__ __forceinline__ uint32_t smem_u32(const void* p) {
    uint32_t a;
    asm("{ .reg .u64 t; cvta.to.shared.u64 t, %1; cvt.u32.u64 %0, t; }" : "=r"(a) : "l"(p));
    return a;
}
__device__ __forceinline__ void cp16(uint32_t dst, const void* src) {
    asm volatile("cp.async.cg.shared.global [%0], [%1], 16;" :: "r"(dst), "l"(src));
}
#define CP_COMMIT() asm volatile("cp.async.commit_group;" ::: "memory")
#define CP_WAIT0()  asm volatile("cp.async.wait_group 0;" ::: "memory")
#define CP_WAIT1()  asm volatile("cp.async.wait_group 1;" ::: "memory")

__device__ __forceinline__ void ldm_x4(uint32_t* r, uint32_t addr) {
    asm volatile("ldmatrix.sync.aligned.m8n8.x4.shared.b16 {%0,%1,%2,%3}, [%4];"
                 : "=r"(r[0]), "=r"(r[1]), "=r"(r[2]), "=r"(r[3]) : "r"(addr));
}
__device__ __forceinline__ void mma_fp16(float* d, const uint32_t* a, const uint32_t* b) {
    asm volatile(
        "mma.sync.aligned.m16n8k16.row.col.f32.f16.f16.f32 "
        "{%0,%1,%2,%3}, {%4,%5,%6,%7}, {%8,%9}, {%0,%1,%2,%3};"
        : "+f"(d[0]), "+f"(d[1]), "+f"(d[2]), "+f"(d[3])
        : "r"(a[0]), "r"(a[1]), "r"(a[2]), "r"(a[3]), "r"(b[0]), "r"(b[1]));
}
// 128B-row tile swizzle: 16B chunk kg (0..7) XOR row&7. Conflict-free for
// the 8-chunk/row cp.async stores and every ldmatrix 8x8 row group.
__device__ __forceinline__ uint32_t tswz(int row, int kg) {
    return (uint32_t)(row * 128 + ((kg ^ (row & 7)) << 4));
}

// ---------------------------------------------------------------------------
// Single-pass fp16 NT GEMM: C = alpha * (A_hi @ B_hi^T) + bias
//   A[M,K], B[N,K] K-major fp16. 3-stage cp.async pipeline, BK=64.
//   Per-z output: fp32 if (f32mask>>z)&1; transposed fp16 (V^T) if
//   (vtmask>>z)&1 (M rows interpreted as batch*4096+seq); else fp16.
// 256 threads, 8 warps (4m x 2n), warp tile 32x64, fp32 register accumulators.
// ---------------------------------------------------------------------------
__global__ __launch_bounds__(256, 2) void mmagemm(
    const __half* __restrict__ Ah, const __half* __restrict__ Bh,
    const float* __restrict__ bias, int biasStride, float alpha,
    float* __restrict__ Cf, __half* __restrict__ Ch, __half* __restrict__ Cvt,
    int K, int N, long long sAB, long long sBB,
    long long sCH, long long sCF, int f32mask, int vtmask)
{
    extern __shared__ char smem[];
    const uint32_t sb = smem_u32(smem);
    const int tid  = threadIdx.x;
    const int lane = tid & 31;
    const int wid  = tid >> 5;
    const int wm   = wid & 3;
    const int wn   = wid >> 2;
    const int z    = blockIdx.z;
    const int m0   = blockIdx.y * BM;
    const int n0   = blockIdx.x * BN;
    const bool wF32 = (f32mask >> z) & 1;
    const bool wVT  = (vtmask >> z) & 1;

    const __half* srcA = Ah + (long long)z * sAB + (long long)m0 * K;
    const __half* srcB = Bh + (long long)z * sBB + (long long)n0 * K;

    float acc[2][8][4];
#pragma unroll
    for (int i = 0; i < 2; i++)
#pragma unroll
        for (int j = 0; j < 8; j++)
#pragma unroll
            for (int q = 0; q < 4; q++) acc[i][j][q] = 0.0f;

    const int KC = K / BK;

    auto load_stage = [&](int s, int k0) {
        const uint32_t base = sb + s * STAGE_B;
#pragma unroll
        for (int h = 0; h < 4; h++) {
            const int c = tid + h * 256;     // 0..1023
            const int row = c >> 3;
            const int kg  = c & 7;
            const uint32_t so = tswz(row, kg);
            const long long go = (long long)row * K + k0 + kg * 8;
            cp16(base + so, srcA + go);
            cp16(base + TILE_B + so, srcB + go);
        }
        CP_COMMIT();
    };

    load_stage(0, 0);
    load_stage(1, BK);

    for (int c = 0; c < KC; ++c) {
        if (c == KC - 1) CP_WAIT0(); else CP_WAIT1();
        __syncthreads();                 // stage c ready; compute c-1 done
        if (c + 2 < KC) {
            const int s2i = c + 2;
            load_stage(s2i % NSTAGE, s2i * BK);
        }

        const uint32_t st = sb + (c % NSTAGE) * STAGE_B;
#pragma unroll
        for (int ks = 0; ks < 4; ++ks) {   // four k16 steps per BK=64
            uint32_t afh[2][4];
#pragma unroll
            for (int mt = 0; mt < 2; ++mt) {
                const int row = wm * 32 + mt * 16 + (lane & 15);
                const int kg  = ks * 2 + (lane >> 4);
                ldm_x4(afh[mt], st + tswz(row, kg));
            }
#pragma unroll
            for (int p = 0; p < 4; ++p) {
                const int n  = wn * 64 + p * 16 + (lane & 7) + ((lane >> 4) & 1) * 8;
                const int kg = ks * 2 + ((lane >> 3) & 1);
                uint32_t bfh[4];
                ldm_x4(bfh, st + TILE_B + tswz(n, kg));
#pragma unroll
                for (int mt = 0; mt < 2; ++mt) {
#pragma unroll
                    for (int s2 = 0; s2 < 2; ++s2)
                        mma_fp16(acc[mt][p * 2 + s2], afh[mt], bfh + s2 * 2);
                }
            }
        }
    }

    // ---- epilogue ----
    const int lr_base = wm * 32 + (lane >> 2);       // CTA-local row
    const int lc_base = wn * 64 + (lane & 3) * 2;    // CTA-local col

    if (wVT) {
        // Transposed fp16 output: V^T[b][h][s]. Stage smem is reused as a
        // 128x128 half tile with pitch TP (conflict-managed).
        __syncthreads();                 // all warps done reading stages
        __half* smt = (__half*)smem;
#pragma unroll
        for (int mt = 0; mt < 2; ++mt) {
#pragma unroll
            for (int nt = 0; nt < 8; ++nt) {
                const int lr = lr_base + mt * 16;
                const int lc = lc_base + nt * 8;
                float v0 = acc[mt][nt][0] * alpha;
                float v1 = acc[mt][nt][1] * alpha;
                float v2 = acc[mt][nt][2] * alpha;
                float v3 = acc[mt][nt][3] * alpha;
                const float b0 = bias[z * biasStride + n0 + lc];
                const float b1 = bias[z * biasStride + n0 + lc + 1];
                v0 += b0; v1 += b1; v2 += b0; v3 += b1;
                smt[(lc + 0) * TP + lr]     = __float2half_rn(v0);
                smt[(lc + 1) * TP + lr]     = __float2half_rn(v1);
                smt[(lc + 0) * TP + lr + 8] = __float2half_rn(v2);
                smt[(lc + 1) * TP + lr + 8] = __float2half_rn(v3);
            }
        }
        __syncthreads();
        const int batch = m0 >> 12;          // m0 / 4096
        const int s0    = m0 & 4095;
        __half* dst = Cvt + (size_t)batch * HID * SEQL;
#pragma unroll
        for (int j = 0; j < 8; ++j) {
            const int orow = (tid >> 4) + j * 16;     // 0..127 (hid-local)
            const int ocol = (tid & 15) * 8;          // 0..120 (seq-local)
            uint4 v = *(const uint4*)&smt[orow * TP + ocol];
            *(uint4*)&dst[(size_t)(n0 + orow) * SEQL + s0 + ocol] = v;
        }
        return;
    }

#pragma unroll
    for (int mt = 0; mt < 2; ++mt) {
#pragma unroll
        for (int nt = 0; nt < 8; ++nt) {
            const int row = m0 + lr_base + mt * 16;
            const int col = n0 + lc_base + nt * 8;
            float v0 = acc[mt][nt][0] * alpha;
            float v1 = acc[mt][nt][1] * alpha;
            float v2 = acc[mt][nt][2] * alpha;
            float v3 = acc[mt][nt][3] * alpha;
            if (bias) {
                const float b0 = bias[z * biasStride + col];
                const float b1 = bias[z * biasStride + col + 1];
                v0 += b0; v1 += b1; v2 += b0; v3 += b1;
            }
            const long long co1 = (long long)row * N + col;
            const long long co2 = co1 + 8ll * N;
            if (wF32) {
                *(float2*)&Cf[z * sCF + co1] = make_float2(v0, v1);
                *(float2*)&Cf[z * sCF + co2] = make_float2(v2, v3);
            } else {
                *(__half2*)&Ch[z * sCH + co1] =
                    __halves2half2(__float2half_rn(v0), __float2half_rn(v1));
                *(__half2*)&Ch[z * sCH + co2] =
                    __halves2half2(__float2half_rn(v2), __float2half_rn(v3));
            }
        }
    }
}

// ---------------------------------------------------------------------------
// fp32 -> fp16 with scale (one float4 per thread).
// ---------------------------------------------------------------------------
__global__ __launch_bounds__(256) void cvt_h(const float* __restrict__ in,
                                             __half* __restrict__ h, float scale)
{
    const long long i = (long long)blockIdx.x * 256 + threadIdx.x;
    float4 v = ((const float4*)in)[i];
    ((__half2*)h)[2 * i + 0] = __halves2half2(__float2half_rn(v.x * scale),
                                              __float2half_rn(v.y * scale));
    ((__half2*)h)[2 * i + 1] = __halves2half2(__float2half_rn(v.z * scale),
                                              __float2half_rn(v.w * scale));
}

__global__ void concat_bias(const float* __restrict__ bq, const float* __restrict__ bk,
                            const float* __restrict__ bv, float* __restrict__ dst)
{
    const int i = blockIdx.x * 256 + threadIdx.x;
    if (i < HID)            dst[i] = bq[i];
    else if (i < 2 * HID)   dst[i] = bk[i - HID];
    else if (i < 3 * HID)   dst[i] = bv[i - 2 * HID];
}

// ---------------------------------------------------------------------------
// Row softmax over fp32 scores -> fp16 hi weights.
// ---------------------------------------------------------------------------
__global__ __launch_bounds__(256) void softmax_h(const float* __restrict__ S,
                                                 __half* __restrict__ Wh)
{
    const float* row = S + (size_t)blockIdx.x * SEQL;
    __half* rh = Wh + (size_t)blockIdx.x * SEQL;
    const int tid = threadIdx.x;
    __shared__ float red[256];

    float vals[16];
    float lmax = -3.402823e38f;
#pragma unroll
    for (int i = 0; i < 4; ++i) {
        float4 t = *(const float4*)&row[(tid + i * 256) * 4];
        vals[i * 4 + 0] = t.x; vals[i * 4 + 1] = t.y;
        vals[i * 4 + 2] = t.z; vals[i * 4 + 3] = t.w;
        lmax = fmaxf(lmax, fmaxf(fmaxf(t.x, t.y), fmaxf(t.z, t.w)));
    }
    red[tid] = lmax;
    __syncthreads();
#pragma unroll
    for (int s = 128; s > 0; s >>= 1) {
        if (tid < s) red[tid] = fmaxf(red[tid], red[tid + s]);
        __syncthreads();
    }
    const float m = red[0];
    __syncthreads();

    float lsum = 0.0f;
#pragma unroll
    for (int i = 0; i < 16; ++i) { vals[i] = expf(vals[i] - m); lsum += vals[i]; }
    red[tid] = lsum;
    __syncthreads();
#pragma unroll
    for (int s = 128; s > 0; s >>= 1) {
        if (tid < s) red[tid] += red[tid + s];
        __syncthreads();
    }
    const float inv = 1.0f / red[0];

#pragma unroll
    for (int i = 0; i < 4; ++i) {
        const int idx = (tid + i * 256) * 4;
        *(__half2*)&rh[idx + 0] = __halves2half2(
            __float2half_rn(vals[i * 4 + 0] * inv), __float2half_rn(vals[i * 4 + 1] * inv));
        *(__half2*)&rh[idx + 2] = __halves2half2(
            __float2half_rn(vals[i * 4 + 2] * inv), __float2half_rn(vals[i * 4 + 3] * inv));
    }
}

// ---------------------------------------------------------------------------
extern "C" void kernel_launch(void* const* d_in, const int* in_sizes, int n_in,
                              void* d_out, int out_size)
{
    (void)in_sizes; (void)n_in; (void)out_size;
    const float* x  = (const float*)d_in[0];
    const float* Wq = (const float*)d_in[1];
    const float* bq = (const float*)d_in[2];
    const float* Wk = (const float*)d_in[3];
    const float* bk = (const float*)d_in[4];
    const float* Wv = (const float*)d_in[5];
    const float* bv = (const float*)d_in[6];
    const float* Wo = (const float*)d_in[7];
    const float* bo = (const float*)d_in[8];
    float* out = (float*)d_out;

    __half *xh, *wh, *qkh, *vth, *ph, *oh;
    float *sf, *bias3;
    cudaGetSymbolAddress((void**)&xh, g_xh);
    cudaGetSymbolAddress((void**)&wh, g_wh);
    cudaGetSymbolAddress((void**)&bias3, g_bias3);
    cudaGetSymbolAddress((void**)&qkh, g_qkh);
    cudaGetSymbolAddress((void**)&vth, g_vth);
    cudaGetSymbolAddress((void**)&sf, g_sf);
    cudaGetSymbolAddress((void**)&ph, g_ph_);
    cudaGetSymbolAddress((void**)&oh, g_oh);

    cudaFuncSetAttribute(mmagemm, cudaFuncAttributeMaxDynamicSharedMemorySize, SMEM_SZ);

    const size_t WELE = (size_t)HID * HID;
    const long long sQKV = (long long)SEQL * HID;
    const long long sS   = (long long)SEQL * SEQL;
    const long long sPL  = (long long)MTOT * HID;   // plane stride
    const float scl = 0.04419417382415922f;         // 1/sqrt(512)

    // ---- input conversions (all single-plane fp16; weights x32) ----
    cvt_h<<<(MTOT * (size_t)HID) / 4 / 256, 256>>>(x, xh, 1.0f);
    cvt_h<<<WELE / 4 / 256, 256>>>(Wq, wh + 0 * WELE, WSCALE);
    cvt_h<<<WELE / 4 / 256, 256>>>(Wk, wh + 1 * WELE, WSCALE);
    cvt_h<<<WELE / 4 / 256, 256>>>(Wv, wh + 2 * WELE, WSCALE);
    cvt_h<<<WELE / 4 / 256, 256>>>(Wo, wh + 3 * WELE, WSCALE);
    concat_bias<<<(3 * HID + 255) / 256, 256>>>(bq, bk, bv, bias3);

    // ---- merged QKV projection: z=0 -> Q hi, z=1 -> K hi, z=2 -> V^T hi ----
    mmagemm<<<dim3(HID / BN, MTOT / BM, 3), 256, SMEM_SZ>>>(
        xh, wh, bias3, HID, INV_WSCALE,
        nullptr, qkh, vth,
        HID, HID, /*sAB*/0, /*sBB*/(long long)WELE,
        /*sCH*/sPL, /*sCF*/0, /*f32mask*/0, /*vtmask*/0b100);

    // ---- scores = Q K^T / sqrt(512) (fp32 out, per-batch z) ----
    mmagemm<<<dim3(SEQL / BN, SEQL / BM, BATCH), 256, SMEM_SZ>>>(
        qkh, qkh + sPL, nullptr, 0, scl,
        sf, nullptr, nullptr,
        HID, SEQL, sQKV, sQKV, 0, sS, 0xF, 0);

    // ---- softmax -> fp16 hi weights ----
    softmax_h<<<BATCH * SEQL, 256>>>(sf, ph);

    // ---- O = weights @ V^T_hi, fp16 hi out ----
    mmagemm<<<dim3(HID / BN, SEQL / BM, BATCH), 256, SMEM_SZ>>>(
        ph, vth, nullptr, 0, 1.0f,
        nullptr, oh, nullptr,
        SEQL, HID, sS, sQKV, sQKV, 0, 0, 0);

    // ---- out = O @ Wo^T_hi + bo (fp32 out) ----
    mmagemm<<<dim3(HID / BN, MTOT / BM, 1), 256, SMEM_SZ>>>(
        oh, wh + 3 * WELE, bo, 0, INV_WSCALE,
        out, nullptr, nullptr,
        HID, HID, 0, 0, 0, 0, 1, 0);
}